// round 5
// baseline (speedup 1.0000x reference)
#include <cuda_runtime.h>
#include <cuda_bf16.h>
#include <stdint.h>
#include <math.h>

// ---------------- scratch buffers (static device memory, no allocs) ----------
#define NTOK 4096              // 4 * 1024 rows
#define HID  1024
__device__ float g_QKV[NTOK * 3 * HID];          // packed Q|K|V rows
__device__ float g_X1 [NTOK * HID];
__device__ float g_F  [NTOK * HID];
__device__ float g_bqkv[3 * HID];
__device__ __nv_bfloat16 g_Ah[NTOK * HID];       // activations hi (x / O / X1)
__device__ __nv_bfloat16 g_Al[NTOK * HID];       // activations lo
__device__ __nv_bfloat16 g_Hh[NTOK * 4 * HID];   // FF hidden hi
__device__ __nv_bfloat16 g_Hl[NTOK * 4 * HID];   // FF hidden lo
__device__ __nv_bfloat16 g_Bh[4 * HID * HID];    // transposed split weights hi
__device__ __nv_bfloat16 g_Bl[4 * HID * HID];    // transposed split weights lo

// ---------------- PTX helpers (arch-neutral only) -----------------------------
__device__ __forceinline__ uint32_t smem_u32(const void* p) {
    uint32_t a;
    asm("{ .reg .u64 t; cvta.to.shared.u64 t, %1; cvt.u32.u64 %0, t; }"
        : "=r"(a) : "l"(p));
    return a;
}
#define CP_ASYNC16(s, g) \
    asm volatile("cp.async.cg.shared.global [%0], [%1], 16;" :: "r"(s), "l"(g))
#define CP_COMMIT() asm volatile("cp.async.commit_group;" ::: "memory")
#define CP_WAIT(n)  asm volatile("cp.async.wait_group %0;" :: "n"(n) : "memory")
#define LDSM_X4(r, addr) \
    asm volatile("ldmatrix.sync.aligned.m8n8.x4.shared.b16 {%0,%1,%2,%3}, [%4];" \
        : "=r"((r)[0]), "=r"((r)[1]), "=r"((r)[2]), "=r"((r)[3]) : "r"(addr))
#define MMA16816(c, a, b0, b1) \
    asm volatile("mma.sync.aligned.m16n8k16.row.col.f32.bf16.bf16.f32 " \
        "{%0,%1,%2,%3}, {%4,%5,%6,%7}, {%8,%9}, {%0,%1,%2,%3};" \
        : "+f"((c)[0]), "+f"((c)[1]), "+f"((c)[2]), "+f"((c)[3]) \
        : "r"((a)[0]), "r"((a)[1]), "r"((a)[2]), "r"((a)[3]), "r"(b0), "r"(b1))
#define FMA2(d, a, b) asm("fma.rn.f32x2 %0, %1, %2, %0;" : "+l"(d) : "l"(a), "l"(b))
#define PACK2(out, x, y) asm("mov.b64 %0, {%1, %2};" : "=l"(out) : "f"(x), "f"(y))
#define UNPACK2(lo, hi, in) asm("mov.b64 {%0, %1}, %2;" : "=f"(lo), "=f"(hi) : "l"(in))

__device__ __forceinline__ void split_bf16(float v, __nv_bfloat16& h, __nv_bfloat16& l) {
    h = __float2bfloat16(v);
    l = __float2bfloat16(v - __bfloat162float(h));
}

// ---------------- conversion kernels -----------------------------------------
__global__ __launch_bounds__(256) void split_kernel(
    const float* __restrict__ A, __nv_bfloat16* __restrict__ H,
    __nv_bfloat16* __restrict__ L, int n4)
{
    int i = blockIdx.x * 256 + threadIdx.x;
    if (i >= n4) return;
    float4 v = ((const float4*)A)[i];
    __nv_bfloat16 h0, h1, h2, h3, l0, l1, l2, l3;
    split_bf16(v.x, h0, l0); split_bf16(v.y, h1, l1);
    split_bf16(v.z, h2, l2); split_bf16(v.w, h3, l3);
    ((__nv_bfloat162*)H)[i * 2 + 0] = __nv_bfloat162(h0, h1);
    ((__nv_bfloat162*)H)[i * 2 + 1] = __nv_bfloat162(h2, h3);
    ((__nv_bfloat162*)L)[i * 2 + 0] = __nv_bfloat162(l0, l1);
    ((__nv_bfloat162*)L)[i * 2 + 1] = __nv_bfloat162(l2, l3);
}

// transpose + split: W [K x N] fp32 -> H/L [N x K] bf16
__global__ __launch_bounds__(256) void tsplit_kernel(
    const float* __restrict__ W, __nv_bfloat16* __restrict__ H,
    __nv_bfloat16* __restrict__ L, int K, int N)
{
    __shared__ float t[32][33];
    const int tx = threadIdx.x, ty = threadIdx.y;
    const int bk = blockIdx.y * 32, bn = blockIdx.x * 32;
    #pragma unroll
    for (int j = 0; j < 4; ++j)
        t[ty + j * 8][tx] = W[(size_t)(bk + ty + j * 8) * N + bn + tx];
    __syncthreads();
    #pragma unroll
    for (int j = 0; j < 4; ++j) {
        int r = ty + j * 8;
        float v = t[tx][r];
        __nv_bfloat16 h, l;
        split_bf16(v, h, l);
        size_t o = (size_t)(bn + r) * K + bk + tx;
        H[o] = h; L[o] = l;
    }
}

// ---------------- bf16-split tensor-core GEMM (mma.sync) ---------------------
// C = act(A @ W + bias); A hi/lo [M,K] row-major, W hi/lo transposed [N,K].
// Output either fp32 (Cf) or bf16 hi/lo (Ch/Cl). Tile 128x128, BK=32, 8 warps.
#define G_PART  8192
#define G_STAGE (4 * G_PART)
#define G_SMEM  (2 * G_STAGE)

__global__ __launch_bounds__(256, 1) void gemm_tc_kernel(
    const __nv_bfloat16* __restrict__ Ah, const __nv_bfloat16* __restrict__ Al,
    const __nv_bfloat16* __restrict__ Bh, const __nv_bfloat16* __restrict__ Bl,
    const float* __restrict__ bias,
    float* __restrict__ Cf, __nv_bfloat16* __restrict__ Ch,
    __nv_bfloat16* __restrict__ Cl,
    int M, int N, int K, int act)
{
    extern __shared__ char smem[];
    const uint32_t sb = smem_u32(smem);
    const int tid = threadIdx.x;
    const int wid = tid >> 5, lane = tid & 31;
    const int warp_m = wid >> 2, warp_n = wid & 3;
    const int bm = blockIdx.y * 128, bn = blockIdx.x * 128;

    float acc[4][4][4];
    #pragma unroll
    for (int i = 0; i < 4; ++i)
        #pragma unroll
        for (int j = 0; j < 4; ++j)
            #pragma unroll
            for (int r = 0; r < 4; ++r) acc[i][j][r] = 0.f;

    const int swz = (lane & 7) >> 1;
    const int rA = warp_m * 64 + ((lane >> 3) & 1) * 8 + (lane & 7);
    const int kA = lane >> 4;
    const int rB = warp_n * 32 + (lane >> 4) * 8 + (lane & 7);
    const int kB = (lane >> 3) & 1;

    const int nst = K >> 5;

    auto load_stage = [&](int j) {
        const uint32_t st = sb + (uint32_t)(j & 1) * G_STAGE;
        const int kc = j * 32;
        #pragma unroll
        for (int t = 0; t < 2; ++t) {
            int idx = tid + t * 256;
            int row = idx >> 2, ch = idx & 3;
            uint32_t so = (uint32_t)row * 64 + (uint32_t)((ch ^ ((row >> 1) & 3)) << 4);
            size_t ga = (size_t)(bm + row) * K + kc + ch * 8;
            size_t gb = (size_t)(bn + row) * K + kc + ch * 8;
            CP_ASYNC16(st + 0 * G_PART + so, Ah + ga);
            CP_ASYNC16(st + 1 * G_PART + so, Al + ga);
            CP_ASYNC16(st + 2 * G_PART + so, Bh + gb);
            CP_ASYNC16(st + 3 * G_PART + so, Bl + gb);
        }
        CP_COMMIT();
    };

    load_stage(0);

    for (int j = 0; j < nst; ++j) {
        if (j + 1 < nst) { load_stage(j + 1); CP_WAIT(1); }
        else             { CP_WAIT(0); }
        __syncthreads();

        const uint32_t st = sb + (uint32_t)(j & 1) * G_STAGE;
        #pragma unroll
        for (int ks = 0; ks < 2; ++ks) {
            uint32_t ah[4][4], al[4][4], bh[2][4], bl[2][4];
            #pragma unroll
            for (int mt = 0; mt < 4; ++mt) {
                uint32_t ao = (uint32_t)(rA + mt * 16) * 64
                            + (uint32_t)(((ks * 2 + kA) ^ swz) << 4);
                LDSM_X4(ah[mt], st + 0 * G_PART + ao);
                LDSM_X4(al[mt], st + 1 * G_PART + ao);
            }
            #pragma unroll
            for (int np = 0; np < 2; ++np) {
                uint32_t bo = (uint32_t)(rB + np * 16) * 64
                            + (uint32_t)(((ks * 2 + kB) ^ swz) << 4);
                LDSM_X4(bh[np], st + 2 * G_PART + bo);
                LDSM_X4(bl[np], st + 3 * G_PART + bo);
            }
            #pragma unroll
            for (int mt = 0; mt < 4; ++mt)
                #pragma unroll
                for (int nt = 0; nt < 4; ++nt) {
                    const uint32_t* bhp = &bh[nt >> 1][(nt & 1) * 2];
                    const uint32_t* blp = &bl[nt >> 1][(nt & 1) * 2];
                    MMA16816(acc[mt][nt], ah[mt], bhp[0], bhp[1]);
                    MMA16816(acc[mt][nt], ah[mt], blp[0], blp[1]);
                    MMA16816(acc[mt][nt], al[mt], bhp[0], bhp[1]);
                }
        }
        __syncthreads();
    }

    // epilogue
    #pragma unroll
    for (int mt = 0; mt < 4; ++mt)
        #pragma unroll
        for (int nt = 0; nt < 4; ++nt) {
            int row0 = bm + warp_m * 64 + mt * 16 + (lane >> 2);
            int col  = bn + warp_n * 32 + nt * 8 + (lane & 3) * 2;
            float b0 = bias[col], b1 = bias[col + 1];
            float v[4];
            v[0] = acc[mt][nt][0] + b0;
            v[1] = acc[mt][nt][1] + b1;
            v[2] = acc[mt][nt][2] + b0;
            v[3] = acc[mt][nt][3] + b1;
            if (act) {
                #pragma unroll
                for (int r = 0; r < 4; ++r)
                    v[r] = 0.5f * v[r] * (1.f + erff(v[r] * 0.70710678118654752f));
            }
            if (Cf) {
                *(float2*)&Cf[(size_t)row0 * N + col]       = make_float2(v[0], v[1]);
                *(float2*)&Cf[(size_t)(row0 + 8) * N + col] = make_float2(v[2], v[3]);
            } else {
                __nv_bfloat16 h0, h1, l0, l1;
                split_bf16(v[0], h0, l0); split_bf16(v[1], h1, l1);
                *(__nv_bfloat162*)&Ch[(size_t)row0 * N + col] = __nv_bfloat162(h0, h1);
                *(__nv_bfloat162*)&Cl[(size_t)row0 * N + col] = __nv_bfloat162(l0, l1);
                split_bf16(v[2], h0, l0); split_bf16(v[3], h1, l1);
                *(__nv_bfloat162*)&Ch[(size_t)(row0 + 8) * N + col] = __nv_bfloat162(h0, h1);
                *(__nv_bfloat162*)&Cl[(size_t)(row0 + 8) * N + col] = __nv_bfloat162(l0, l1);
            }
        }
}

// ---------------- fused attention with head-axis softmax ---------------------
// Reads packed QKV [4096 rows x 3072]; writes O as bf16 hi/lo.
// grid (a=64, n=4), 512 threads: h = tid>>5 (warp = head), bg = (tid>>3)&3,
// dq = tid&7. Each thread: 4 b-rows x 8 d (cols dq*4 + m*32).
#define SC(h, b, bp) ((h) * 272 + (b) * 17 + (bp))
#define BUFSTRIDE 1040

__global__ __launch_bounds__(512, 1) void attn_kernel(
    const float* __restrict__ QKV,
    __nv_bfloat16* __restrict__ Oh, __nv_bfloat16* __restrict__ Ol)
{
    extern __shared__ float sm[];
    float* buf = sm;                       // 16*1040 floats
    float* sc  = sm + 16 * BUFSTRIDE;      // 16*272 floats

    const int tid = threadIdx.x;
    const int h  = tid >> 5;
    const int bg = (tid >> 3) & 3;
    const int dq = tid & 7;
    const int a = blockIdx.x;
    const int n = blockIdx.y;
    const float scale = 0.03125f;

    const size_t rowbase = (size_t)n * 1024 * 3072;

    // q (scaled): 4 b-rows x 8 d
    unsigned long long q2[4][4];
    #pragma unroll
    for (int i = 0; i < 4; ++i) {
        const float* qrow = QKV + rowbase + (size_t)(h * 64 + a) * 3072
                              + (bg * 4 + i) * 64 + dq * 4;
        #pragma unroll
        for (int m = 0; m < 2; ++m) {
            float4 t = *(const float4*)(qrow + m * 32);
            t.x *= scale; t.y *= scale; t.z *= scale; t.w *= scale;
            PACK2(q2[i][m * 2 + 0], t.x, t.y);
            PACK2(q2[i][m * 2 + 1], t.z, t.w);
        }
    }

    unsigned long long acc2[4][4];
    #pragma unroll
    for (int i = 0; i < 4; ++i)
        #pragma unroll
        for (int p = 0; p < 4; ++p) acc2[i][p] = 0ULL;

    for (int ap = 0; ap < 64; ++ap) {
        __syncthreads();

        // stage K rows (head i -> QKV row i*64+ap, cols [1024,2048))
        #pragma unroll
        for (int r = 0; r < 8; ++r) {
            int flat = (r * 512 + tid) * 4;
            int row = flat >> 10, col = flat & 1023;
            *(float4*)&buf[row * BUFSTRIDE + col] =
                *(const float4*)(QKV + rowbase + (size_t)(row * 64 + ap) * 3072
                                 + 1024 + col);
        }
        __syncthreads();

        // scores
        {
            const float* kh = buf + h * BUFSTRIDE;
            #pragma unroll
            for (int bp = 0; bp < 16; ++bp) {
                ulonglong2 kv0 = *(const ulonglong2*)(kh + bp * 64 + dq * 4);
                ulonglong2 kv1 = *(const ulonglong2*)(kh + bp * 64 + dq * 4 + 32);
                unsigned long long kp[4] = {kv0.x, kv0.y, kv1.x, kv1.y};
                unsigned long long s2[4] = {0ULL, 0ULL, 0ULL, 0ULL};
                #pragma unroll
                for (int p = 0; p < 4; ++p)
                    #pragma unroll
                    for (int i = 0; i < 4; ++i)
                        FMA2(s2[i], q2[i][p], kp[p]);

                float sf[4];
                #pragma unroll
                for (int i = 0; i < 4; ++i) {
                    float lo, hi;
                    UNPACK2(lo, hi, s2[i]);
                    sf[i] = lo + hi;
                    sf[i] += __shfl_xor_sync(0xffffffffu, sf[i], 1);
                    sf[i] += __shfl_xor_sync(0xffffffffu, sf[i], 2);
                    sf[i] += __shfl_xor_sync(0xffffffffu, sf[i], 4);
                }
                if (dq < 4) {
                    float s0 = (dq & 1) ? sf[1] : sf[0];
                    float s1 = (dq & 1) ? sf[3] : sf[2];
                    float myv = (dq & 2) ? s1 : s0;
                    sc[SC(h, bg * 4 + dq, bp)] = myv;
                }
            }
        }
        __syncthreads();

        // stage V rows (cols [2048,3072))
        #pragma unroll
        for (int r = 0; r < 8; ++r) {
            int flat = (r * 512 + tid) * 4;
            int row = flat >> 10, col = flat & 1023;
            *(float4*)&buf[row * BUFSTRIDE + col] =
                *(const float4*)(QKV + rowbase + (size_t)(row * 64 + ap) * 3072
                                 + 2048 + col);
        }

        // head-softmax on sc (threads 0..255 own one (b, b') pair each)
        if (tid < 256) {
            const int pb = tid >> 4, pbp = tid & 15;
            float m = -1e30f;
            #pragma unroll
            for (int hh = 0; hh < 16; ++hh) m = fmaxf(m, sc[SC(hh, pb, pbp)]);
            float ssum = 0.f;
            #pragma unroll
            for (int hh = 0; hh < 16; ++hh) {
                float e = __expf(sc[SC(hh, pb, pbp)] - m);
                ssum += e;
                sc[SC(hh, pb, pbp)] = e;
            }
            float inv = 1.f / ssum;
            #pragma unroll
            for (int hh = 0; hh < 16; ++hh) sc[SC(hh, pb, pbp)] *= inv;
        }
        __syncthreads();

        // AV accumulate
        {
            const float* vh = buf + h * BUFSTRIDE;
            #pragma unroll
            for (int bp = 0; bp < 16; ++bp) {
                ulonglong2 vv0 = *(const ulonglong2*)(vh + bp * 64 + dq * 4);
                ulonglong2 vv1 = *(const ulonglong2*)(vh + bp * 64 + dq * 4 + 32);
                unsigned long long vp[4] = {vv0.x, vv0.y, vv1.x, vv1.y};
                #pragma unroll
                for (int i = 0; i < 4; ++i) {
                    float w = sc[SC(h, bg * 4 + i, bp)];
                    unsigned long long w2;
                    PACK2(w2, w, w);
                    #pragma unroll
                    for (int p = 0; p < 4; ++p)
                        FMA2(acc2[i][p], w2, vp[p]);
                }
            }
        }
    }

    // write O as bf16 hi/lo (rows of the [4096 x 1024] activation buffers)
    #pragma unroll
    for (int i = 0; i < 4; ++i) {
        size_t oo = (size_t)((n * 1024) + h * 64 + a) * 1024 + (bg * 4 + i) * 64 + dq * 4;
        #pragma unroll
        for (int m = 0; m < 2; ++m) {
            float v0, v1, v2, v3;
            UNPACK2(v0, v1, acc2[i][m * 2 + 0]);
            UNPACK2(v2, v3, acc2[i][m * 2 + 1]);
            __nv_bfloat16 h0, h1, h2, h3, l0, l1, l2, l3;
            split_bf16(v0, h0, l0); split_bf16(v1, h1, l1);
            split_bf16(v2, h2, l2); split_bf16(v3, h3, l3);
            *(__nv_bfloat162*)(Oh + oo + m * 32)     = __nv_bfloat162(h0, h1);
            *(__nv_bfloat162*)(Oh + oo + m * 32 + 2) = __nv_bfloat162(h2, h3);
            *(__nv_bfloat162*)(Ol + oo + m * 32)     = __nv_bfloat162(l0, l1);
            *(__nv_bfloat162*)(Ol + oo + m * 32 + 2) = __nv_bfloat162(l2, l3);
        }
    }
}

// ---------------- fused residual + LayerNorm (+ optional hi/lo emit) ---------
__global__ __launch_bounds__(256) void ln_kernel(
    const float* __restrict__ A, const float* __restrict__ R,
    const float* __restrict__ g, const float* __restrict__ bta,
    float* __restrict__ out, __nv_bfloat16* __restrict__ Xh,
    __nv_bfloat16* __restrict__ Xl)
{
    __shared__ float red[16];
    const int row = blockIdx.x;
    const int tid = threadIdx.x;

    float4 v = ((const float4*)(A + (size_t)row * 1024))[tid];
    float4 r = ((const float4*)(R + (size_t)row * 1024))[tid];
    v.x += r.x; v.y += r.y; v.z += r.z; v.w += r.w;

    float s  = v.x + v.y + v.z + v.w;
    float sq = v.x * v.x + v.y * v.y + v.z * v.z + v.w * v.w;
    #pragma unroll
    for (int o = 16; o > 0; o >>= 1) {
        s  += __shfl_xor_sync(0xffffffffu, s,  o);
        sq += __shfl_xor_sync(0xffffffffu, sq, o);
    }
    if ((tid & 31) == 0) { red[tid >> 5] = s; red[8 + (tid >> 5)] = sq; }
    __syncthreads();
    float S = 0.f, SQ = 0.f;
    #pragma unroll
    for (int w = 0; w < 8; ++w) { S += red[w]; SQ += red[8 + w]; }

    const float mean = S * (1.f / 1024.f);
    const float var  = SQ * (1.f / 1024.f) - mean * mean;
    const float rstd = rsqrtf(var + 1e-5f);

    float4 gv = ((const float4*)g)[tid];
    float4 bv = ((const float4*)bta)[tid];
    float4 o;
    o.x = (v.x - mean) * rstd * gv.x + bv.x;
    o.y = (v.y - mean) * rstd * gv.y + bv.y;
    o.z = (v.z - mean) * rstd * gv.z + bv.z;
    o.w = (v.w - mean) * rstd * gv.w + bv.w;
    ((float4*)(out + (size_t)row * 1024))[tid] = o;

    if (Xh) {
        __nv_bfloat16 h0, h1, h2, h3, l0, l1, l2, l3;
        split_bf16(o.x, h0, l0); split_bf16(o.y, h1, l1);
        split_bf16(o.z, h2, l2); split_bf16(o.w, h3, l3);
        size_t oo = (size_t)row * 1024 + tid * 4;
        *(__nv_bfloat162*)(Xh + oo)     = __nv_bfloat162(h0, h1);
        *(__nv_bfloat162*)(Xh + oo + 2) = __nv_bfloat162(h2, h3);
        *(__nv_bfloat162*)(Xl + oo)     = __nv_bfloat162(l0, l1);
        *(__nv_bfloat162*)(Xl + oo + 2) = __nv_bfloat162(l2, l3);
    }
}

// ---------------- launch ------------------------------------------------------
extern "C" void kernel_launch(void* const* d_in, const int* in_sizes, int n_in,
                              void* d_out, int out_size)
{
    const float* x  = (const float*)d_in[0];
    const float* Wq = (const float*)d_in[1];
    const float* bq = (const float*)d_in[2];
    const float* Wk = (const float*)d_in[3];
    const float* bk = (const float*)d_in[4];
    const float* Wv = (const float*)d_in[5];
    const float* bv = (const float*)d_in[6];
    const float* Wo = (const float*)d_in[7];
    const float* bo = (const float*)d_in[8];
    const float* g1 = (const float*)d_in[9];
    const float* b1 = (const float*)d_in[10];
    const float* W1 = (const float*)d_in[11];
    const float* c1 = (const float*)d_in[12];
    const float* W2 = (const float*)d_in[13];
    const float* c2 = (const float*)d_in[14];
    const float* g2 = (const float*)d_in[15];
    const float* b2 = (const float*)d_in[16];
    float* out = (float*)d_out;

    float *pQKV, *pX1, *pF, *pbqkv;
    __nv_bfloat16 *pAh, *pAl, *pHh, *pHl, *pBh, *pBl;
    cudaGetSymbolAddress((void**)&pQKV, g_QKV);
    cudaGetSymbolAddress((void**)&pX1,  g_X1);
    cudaGetSymbolAddress((void**)&pF,   g_F);
    cudaGetSymbolAddress((void**)&pbqkv,g_bqkv);
    cudaGetSymbolAddress((void**)&pAh,  g_Ah);
    cudaGetSymbolAddress((void**)&pAl,  g_Al);
    cudaGetSymbolAddress((void**)&pHh,  g_Hh);
    cudaGetSymbolAddress((void**)&pHl,  g_Hl);
    cudaGetSymbolAddress((void**)&pBh,  g_Bh);
    cudaGetSymbolAddress((void**)&pBl,  g_Bl);

    const int ATTN_SMEM = (16 * BUFSTRIDE + 16 * 272) * 4;
    cudaFuncSetAttribute(attn_kernel, cudaFuncAttributeMaxDynamicSharedMemorySize, ATTN_SMEM);
    cudaFuncSetAttribute(gemm_tc_kernel, cudaFuncAttributeMaxDynamicSharedMemorySize, G_SMEM);

    dim3 blk(256);
    dim3 t32(32, 8);
    const int n4_1 = NTOK * HID / 4;
    dim3 gs1((n4_1 + 255) / 256);
    dim3 tg11(HID / 32, HID / 32);
    dim3 tg14(4 * HID / 32, HID / 32);
    dim3 tg41(HID / 32, 4 * HID / 32);
    dim3 ggqkv(3 * HID / 128, NTOK / 128);    // N=3072
    dim3 gg1(HID / 128, NTOK / 128);          // N=1024
    dim3 gg4(4 * HID / 128, NTOK / 128);      // N=4096

    // ---- QKV (fused): split x, transpose Wq|Wk|Wv into one [3072,1024] B ----
    split_kernel<<<gs1, blk>>>(x, pAh, pAl, n4_1);
    tsplit_kernel<<<tg11, t32>>>(Wq, pBh,               pBl,               HID, HID);
    tsplit_kernel<<<tg11, t32>>>(Wk, pBh + 1024 * 1024, pBl + 1024 * 1024, HID, HID);
    tsplit_kernel<<<tg11, t32>>>(Wv, pBh + 2048 * 1024, pBl + 2048 * 1024, HID, HID);
    cudaMemcpyAsync(pbqkv,        bq, HID * 4, cudaMemcpyDeviceToDevice, 0);
    cudaMemcpyAsync(pbqkv + 1024, bk, HID * 4, cudaMemcpyDeviceToDevice, 0);
    cudaMemcpyAsync(pbqkv + 2048, bv, HID * 4, cudaMemcpyDeviceToDevice, 0);
    gemm_tc_kernel<<<ggqkv, blk, G_SMEM>>>(pAh, pAl, pBh, pBl, pbqkv,
                                           pQKV, nullptr, nullptr,
                                           NTOK, 3 * HID, HID, 0);

    // ---- attention (head-axis softmax); emits O hi/lo directly -------------
    attn_kernel<<<dim3(64, 4), 512, ATTN_SMEM>>>(pQKV, pAh, pAl);

    // ---- output projection, residual + LN1 (emits X1 fp32 + hi/lo) ---------
    tsplit_kernel<<<tg11, t32>>>(Wo, pBh, pBl, HID, HID);
    gemm_tc_kernel<<<gg1, blk, G_SMEM>>>(pAh, pAl, pBh, pBl, bo,
                                         pF, nullptr, nullptr,
                                         NTOK, HID, HID, 0);
    ln_kernel<<<NTOK, blk>>>(pF, x, g1, b1, pX1, pAh, pAl);

    // ---- FFN: FF1 emits GELU(H) hi/lo; FF2 back to fp32 --------------------
    tsplit_kernel<<<tg14, t32>>>(W1, pBh, pBl, HID, 4 * HID);
    gemm_tc_kernel<<<gg4, blk, G_SMEM>>>(pAh, pAl, pBh, pBl, c1,
                                         nullptr, pHh, pHl,
                                         NTOK, 4 * HID, HID, 1);
    tsplit_kernel<<<tg41, t32>>>(W2, pBh, pBl, 4 * HID, HID);
    gemm_tc_kernel<<<gg1, blk, G_SMEM>>>(pHh, pHl, pBh, pBl, c2,
                                         pF, nullptr, nullptr,
                                         NTOK, HID, 4 * HID, 0);

    // ---- residual + LN2 -> output -------------------------------------------
    ln_kernel<<<NTOK, blk>>>(pF, pX1, g2, b2, out, nullptr, nullptr);
}

// round 6
// speedup vs baseline: 1.3414x; 1.3414x over previous
#include <cuda_runtime.h>
#include <cuda_bf16.h>
#include <stdint.h>
#include <math.h>

// ---------------- scratch buffers (static device memory, no allocs) ----------
#define NTOK 4096              // 4 * 1024 rows
#define HID  1024
__device__ float g_X1 [NTOK * HID];
__device__ float g_F  [NTOK * HID];
__device__ float g_bqkv[3 * HID];
__device__ __nv_bfloat16 g_Ah[NTOK * HID];       // activations hi (x / O / X1)
__device__ __nv_bfloat16 g_Al[NTOK * HID];       // activations lo
__device__ __nv_bfloat16 g_Hh[NTOK * 4 * HID];   // QKV hi, later FF hidden hi
__device__ __nv_bfloat16 g_Hl[NTOK * 4 * HID];   // QKV lo, later FF hidden lo
__device__ __nv_bfloat16 g_Bh[4 * HID * HID];    // transposed split weights hi
__device__ __nv_bfloat16 g_Bl[4 * HID * HID];    // transposed split weights lo

// ---------------- PTX helpers (arch-neutral only) -----------------------------
__device__ __forceinline__ uint32_t smem_u32(const void* p) {
    uint32_t a;
    asm("{ .reg .u64 t; cvta.to.shared.u64 t, %1; cvt.u32.u64 %0, t; }"
        : "=r"(a) : "l"(p));
    return a;
}
#define CP_ASYNC16(s, g) \
    asm volatile("cp.async.cg.shared.global [%0], [%1], 16;" :: "r"(s), "l"(g))
#define CP_COMMIT() asm volatile("cp.async.commit_group;" ::: "memory")
#define CP_WAIT(n)  asm volatile("cp.async.wait_group %0;" :: "n"(n) : "memory")
#define LDSM_X4(r, addr) \
    asm volatile("ldmatrix.sync.aligned.m8n8.x4.shared.b16 {%0,%1,%2,%3}, [%4];" \
        : "=r"((r)[0]), "=r"((r)[1]), "=r"((r)[2]), "=r"((r)[3]) : "r"(addr))
#define LDSM_X2(r, addr) \
    asm volatile("ldmatrix.sync.aligned.m8n8.x2.shared.b16 {%0,%1}, [%2];" \
        : "=r"((r)[0]), "=r"((r)[1]) : "r"(addr))
#define LDSM_X2T(r, addr) \
    asm volatile("ldmatrix.sync.aligned.m8n8.x2.trans.shared.b16 {%0,%1}, [%2];" \
        : "=r"((r)[0]), "=r"((r)[1]) : "r"(addr))
#define MMA16816(c, a, b0, b1) \
    asm volatile("mma.sync.aligned.m16n8k16.row.col.f32.bf16.bf16.f32 " \
        "{%0,%1,%2,%3}, {%4,%5,%6,%7}, {%8,%9}, {%0,%1,%2,%3};" \
        : "+f"((c)[0]), "+f"((c)[1]), "+f"((c)[2]), "+f"((c)[3]) \
        : "r"((a)[0]), "r"((a)[1]), "r"((a)[2]), "r"((a)[3]), "r"(b0), "r"(b1))

__device__ __forceinline__ void split_bf16(float v, __nv_bfloat16& h, __nv_bfloat16& l) {
    h = __float2bfloat16(v);
    l = __float2bfloat16(v - __bfloat162float(h));
}
__device__ __forceinline__ uint32_t pack_bf2(__nv_bfloat16 x, __nv_bfloat16 y) {
    __nv_bfloat162 p(x, y);
    return *reinterpret_cast<uint32_t*>(&p);
}

// ---------------- conversion kernels -----------------------------------------
__global__ __launch_bounds__(256) void split_kernel(
    const float* __restrict__ A, __nv_bfloat16* __restrict__ H,
    __nv_bfloat16* __restrict__ L, int n4)
{
    int i = blockIdx.x * 256 + threadIdx.x;
    if (i >= n4) return;
    float4 v = ((const float4*)A)[i];
    __nv_bfloat16 h0, h1, h2, h3, l0, l1, l2, l3;
    split_bf16(v.x, h0, l0); split_bf16(v.y, h1, l1);
    split_bf16(v.z, h2, l2); split_bf16(v.w, h3, l3);
    ((__nv_bfloat162*)H)[i * 2 + 0] = __nv_bfloat162(h0, h1);
    ((__nv_bfloat162*)H)[i * 2 + 1] = __nv_bfloat162(h2, h3);
    ((__nv_bfloat162*)L)[i * 2 + 0] = __nv_bfloat162(l0, l1);
    ((__nv_bfloat162*)L)[i * 2 + 1] = __nv_bfloat162(l2, l3);
}

// transpose + split: W [K x N] fp32 -> H/L [N x K] bf16
__global__ __launch_bounds__(256) void tsplit_kernel(
    const float* __restrict__ W, __nv_bfloat16* __restrict__ H,
    __nv_bfloat16* __restrict__ L, int K, int N)
{
    __shared__ float t[32][33];
    const int tx = threadIdx.x, ty = threadIdx.y;
    const int bk = blockIdx.y * 32, bn = blockIdx.x * 32;
    #pragma unroll
    for (int j = 0; j < 4; ++j)
        t[ty + j * 8][tx] = W[(size_t)(bk + ty + j * 8) * N + bn + tx];
    __syncthreads();
    #pragma unroll
    for (int j = 0; j < 4; ++j) {
        int r = ty + j * 8;
        float v = t[tx][r];
        __nv_bfloat16 h, l;
        split_bf16(v, h, l);
        size_t o = (size_t)(bn + r) * K + bk + tx;
        H[o] = h; L[o] = l;
    }
}

// ---------------- bf16-split tensor-core GEMM (mma.sync) ---------------------
#define G_PART  8192
#define G_STAGE (4 * G_PART)
#define G_SMEM  (2 * G_STAGE)

__global__ __launch_bounds__(256, 1) void gemm_tc_kernel(
    const __nv_bfloat16* __restrict__ Ah, const __nv_bfloat16* __restrict__ Al,
    const __nv_bfloat16* __restrict__ Bh, const __nv_bfloat16* __restrict__ Bl,
    const float* __restrict__ bias,
    float* __restrict__ Cf, __nv_bfloat16* __restrict__ Ch,
    __nv_bfloat16* __restrict__ Cl,
    int M, int N, int K, int act)
{
    extern __shared__ char smem[];
    const uint32_t sb = smem_u32(smem);
    const int tid = threadIdx.x;
    const int wid = tid >> 5, lane = tid & 31;
    const int warp_m = wid >> 2, warp_n = wid & 3;
    const int bm = blockIdx.y * 128, bn = blockIdx.x * 128;

    float acc[4][4][4];
    #pragma unroll
    for (int i = 0; i < 4; ++i)
        #pragma unroll
        for (int j = 0; j < 4; ++j)
            #pragma unroll
            for (int r = 0; r < 4; ++r) acc[i][j][r] = 0.f;

    const int swz = (lane & 7) >> 1;
    const int rA = warp_m * 64 + ((lane >> 3) & 1) * 8 + (lane & 7);
    const int kA = lane >> 4;
    const int rB = warp_n * 32 + (lane >> 4) * 8 + (lane & 7);
    const int kB = (lane >> 3) & 1;

    const int nst = K >> 5;

    auto load_stage = [&](int j) {
        const uint32_t st = sb + (uint32_t)(j & 1) * G_STAGE;
        const int kc = j * 32;
        #pragma unroll
        for (int t = 0; t < 2; ++t) {
            int idx = tid + t * 256;
            int row = idx >> 2, ch = idx & 3;
            uint32_t so = (uint32_t)row * 64 + (uint32_t)((ch ^ ((row >> 1) & 3)) << 4);
            size_t ga = (size_t)(bm + row) * K + kc + ch * 8;
            size_t gb = (size_t)(bn + row) * K + kc + ch * 8;
            CP_ASYNC16(st + 0 * G_PART + so, Ah + ga);
            CP_ASYNC16(st + 1 * G_PART + so, Al + ga);
            CP_ASYNC16(st + 2 * G_PART + so, Bh + gb);
            CP_ASYNC16(st + 3 * G_PART + so, Bl + gb);
        }
        CP_COMMIT();
    };

    load_stage(0);

    for (int j = 0; j < nst; ++j) {
        if (j + 1 < nst) { load_stage(j + 1); CP_WAIT(1); }
        else             { CP_WAIT(0); }
        __syncthreads();

        const uint32_t st = sb + (uint32_t)(j & 1) * G_STAGE;
        #pragma unroll
        for (int ks = 0; ks < 2; ++ks) {
            uint32_t ah[4][4], al[4][4], bh[2][4], bl[2][4];
            #pragma unroll
            for (int mt = 0; mt < 4; ++mt) {
                uint32_t ao = (uint32_t)(rA + mt * 16) * 64
                            + (uint32_t)(((ks * 2 + kA) ^ swz) << 4);
                LDSM_X4(ah[mt], st + 0 * G_PART + ao);
                LDSM_X4(al[mt], st + 1 * G_PART + ao);
            }
            #pragma unroll
            for (int np = 0; np < 2; ++np) {
                uint32_t bo = (uint32_t)(rB + np * 16) * 64
                            + (uint32_t)(((ks * 2 + kB) ^ swz) << 4);
                LDSM_X4(bh[np], st + 2 * G_PART + bo);
                LDSM_X4(bl[np], st + 3 * G_PART + bo);
            }
            #pragma unroll
            for (int mt = 0; mt < 4; ++mt)
                #pragma unroll
                for (int nt = 0; nt < 4; ++nt) {
                    const uint32_t* bhp = &bh[nt >> 1][(nt & 1) * 2];
                    const uint32_t* blp = &bl[nt >> 1][(nt & 1) * 2];
                    MMA16816(acc[mt][nt], ah[mt], bhp[0], bhp[1]);
                    MMA16816(acc[mt][nt], ah[mt], blp[0], blp[1]);
                    MMA16816(acc[mt][nt], al[mt], bhp[0], bhp[1]);
                }
        }
        __syncthreads();
    }

    // epilogue
    #pragma unroll
    for (int mt = 0; mt < 4; ++mt)
        #pragma unroll
        for (int nt = 0; nt < 4; ++nt) {
            int row0 = bm + warp_m * 64 + mt * 16 + (lane >> 2);
            int col  = bn + warp_n * 32 + nt * 8 + (lane & 3) * 2;
            float b0 = bias[col], b1 = bias[col + 1];
            float v[4];
            v[0] = acc[mt][nt][0] + b0;
            v[1] = acc[mt][nt][1] + b1;
            v[2] = acc[mt][nt][2] + b0;
            v[3] = acc[mt][nt][3] + b1;
            if (act) {
                #pragma unroll
                for (int r = 0; r < 4; ++r)
                    v[r] = 0.5f * v[r] * (1.f + erff(v[r] * 0.70710678118654752f));
            }
            if (Cf) {
                *(float2*)&Cf[(size_t)row0 * N + col]       = make_float2(v[0], v[1]);
                *(float2*)&Cf[(size_t)(row0 + 8) * N + col] = make_float2(v[2], v[3]);
            } else {
                __nv_bfloat16 h0, h1, l0, l1;
                split_bf16(v[0], h0, l0); split_bf16(v[1], h1, l1);
                *(__nv_bfloat162*)&Ch[(size_t)row0 * N + col] = __nv_bfloat162(h0, h1);
                *(__nv_bfloat162*)&Cl[(size_t)row0 * N + col] = __nv_bfloat162(l0, l1);
                split_bf16(v[2], h0, l0); split_bf16(v[3], h1, l1);
                *(__nv_bfloat162*)&Ch[(size_t)(row0 + 8) * N + col] = __nv_bfloat162(h0, h1);
                *(__nv_bfloat162*)&Cl[(size_t)(row0 + 8) * N + col] = __nv_bfloat162(l0, l1);
            }
        }
}

// ---------------- tensor-core attention with head-axis softmax ----------------
// QKV packed bf16 hi/lo [4096][3072]. Per block (a, n): 16 warps, warp = head.
// Per head: scores[16,16] = Q[16,64] @ K[16,64]^T (split, 3 MMAs per k-step),
// head-softmax across warps via smem, O[16,64] += W[16,16] @ V[16,64] (split).
// smem: bufH/bufL 32KB each (Q then K then V tiles, xor-swizzled 128B rows),
// sc fp32 scores [16][16][18] padded (head stride 290).
#define SCW(hh, b, p) ((hh) * 290 + (b) * 18 + (p))
#define ATTN_SMEM (65536 + 290 * 16 * 4)

__global__ __launch_bounds__(512, 1) void attn_kernel(
    const __nv_bfloat16* __restrict__ Ph, const __nv_bfloat16* __restrict__ Pl,
    __nv_bfloat16* __restrict__ Oh, __nv_bfloat16* __restrict__ Ol)
{
    extern __shared__ char smem[];
    const uint32_t sbH = smem_u32(smem);
    const uint32_t sbL = sbH + 32768;
    float* sc = (float*)(smem + 65536);

    const int tid = threadIdx.x, lane = tid & 31, h = tid >> 5;
    const int a = blockIdx.x, n = blockIdx.y;
    const int lr = lane >> 2, lc = lane & 3;

    // stage 16 head-rows (hi+lo) of one QKV section into swizzled smem
    auto stage = [&](int rowsel, int colbase) {
        #pragma unroll
        for (int t = 0; t < 4; ++t) {
            int f = tid + t * 512;
            int hh = f >> 7, s = f & 127, bp = s >> 3, c = s & 7;
            uint32_t dst = (uint32_t)hh * 2048 + bp * 128 + ((c ^ (bp & 7)) << 4);
            size_t src = (size_t)(n * 1024 + hh * 64 + rowsel) * 3072
                       + colbase + bp * 64 + c * 8;
            CP_ASYNC16(sbH + dst, Ph + src);
            CP_ASYNC16(sbL + dst, Pl + src);
        }
        CP_COMMIT();
    };

    // ---- Q fragments (held in registers for the whole block) ----
    stage(a, 0);
    CP_WAIT(0); __syncthreads();
    uint32_t qh[4][4], ql[4][4];
    {
        int b = lane & 15, csel = lane >> 4;
        #pragma unroll
        for (int ks = 0; ks < 4; ++ks) {
            uint32_t ad = (uint32_t)h * 2048 + b * 128
                        + (((ks * 2 + csel) ^ (b & 7)) << 4);
            LDSM_X4(qh[ks], sbH + ad);
            LDSM_X4(ql[ks], sbL + ad);
        }
    }

    float o[8][4];
    #pragma unroll
    for (int nt = 0; nt < 8; ++nt)
        #pragma unroll
        for (int r = 0; r < 4; ++r) o[nt][r] = 0.f;

    for (int ap = 0; ap < 64; ++ap) {
        __syncthreads();                       // prev iter done with buffers
        stage(ap, 1024);                       // K tiles
        CP_WAIT(0); __syncthreads();

        // ---- scores: S = Q K^T (split: hh + hl + lh) ----
        float s[2][4];
        #pragma unroll
        for (int nt = 0; nt < 2; ++nt)
            #pragma unroll
            for (int r = 0; r < 4; ++r) s[nt][r] = 0.f;

        {
            int bpr = (lane & 7);
            int khalf = (lane >> 3) & 1;
            #pragma unroll
            for (int ks = 0; ks < 4; ++ks)
                #pragma unroll
                for (int nt = 0; nt < 2; ++nt) {
                    int row = nt * 8 + bpr;
                    uint32_t ad = (uint32_t)h * 2048 + row * 128
                                + (((ks * 2 + khalf) ^ (row & 7)) << 4);
                    uint32_t kh2[2], kl2[2];
                    LDSM_X2(kh2, sbH + ad);
                    LDSM_X2(kl2, sbL + ad);
                    MMA16816(s[nt], qh[ks], kh2[0], kh2[1]);
                    MMA16816(s[nt], qh[ks], kl2[0], kl2[1]);
                    MMA16816(s[nt], ql[ks], kh2[0], kh2[1]);
                }
        }
        #pragma unroll
        for (int nt = 0; nt < 2; ++nt) {
            int c0 = nt * 8 + 2 * lc;
            sc[SCW(h, lr,     c0)]     = s[nt][0] * 0.03125f;
            sc[SCW(h, lr,     c0 + 1)] = s[nt][1] * 0.03125f;
            sc[SCW(h, lr + 8, c0)]     = s[nt][2] * 0.03125f;
            sc[SCW(h, lr + 8, c0 + 1)] = s[nt][3] * 0.03125f;
        }
        __syncthreads();

        stage(ap, 2048);                       // V tiles (overlap with softmax)

        // ---- head-softmax: thread p owns (b = p>>4, b' = p&15) ----
        if (tid < 256) {
            const int pb = tid >> 4, pbp = tid & 15;
            float m = -1e30f;
            #pragma unroll
            for (int hh = 0; hh < 16; ++hh) m = fmaxf(m, sc[SCW(hh, pb, pbp)]);
            float ssum = 0.f;
            #pragma unroll
            for (int hh = 0; hh < 16; ++hh) {
                float e = __expf(sc[SCW(hh, pb, pbp)] - m);
                ssum += e;
                sc[SCW(hh, pb, pbp)] = e;
            }
            float inv = 1.f / ssum;
            #pragma unroll
            for (int hh = 0; hh < 16; ++hh) sc[SCW(hh, pb, pbp)] *= inv;
        }
        CP_WAIT(0); __syncthreads();

        // ---- W fragments (A m16k16) from softmaxed scores ----
        uint32_t awh[4], awl[4];
        {
            float wv[8];
            wv[0] = sc[SCW(h, lr,     2 * lc)];
            wv[1] = sc[SCW(h, lr,     2 * lc + 1)];
            wv[2] = sc[SCW(h, lr + 8, 2 * lc)];
            wv[3] = sc[SCW(h, lr + 8, 2 * lc + 1)];
            wv[4] = sc[SCW(h, lr,     2 * lc + 8)];
            wv[5] = sc[SCW(h, lr,     2 * lc + 9)];
            wv[6] = sc[SCW(h, lr + 8, 2 * lc + 8)];
            wv[7] = sc[SCW(h, lr + 8, 2 * lc + 9)];
            #pragma unroll
            for (int i = 0; i < 4; ++i) {
                __nv_bfloat16 h0, h1, l0, l1;
                split_bf16(wv[2 * i],     h0, l0);
                split_bf16(wv[2 * i + 1], h1, l1);
                awh[i] = pack_bf2(h0, h1);
                awl[i] = pack_bf2(l0, l1);
            }
        }

        // ---- AV: O += W V (V via ldmatrix.trans; split) ----
        {
            int bp = lane & 15;
            #pragma unroll
            for (int nt = 0; nt < 8; ++nt) {
                uint32_t ad = (uint32_t)h * 2048 + bp * 128
                            + ((nt ^ (bp & 7)) << 4);
                uint32_t vh2[2], vl2[2];
                LDSM_X2T(vh2, sbH + ad);
                LDSM_X2T(vl2, sbL + ad);
                MMA16816(o[nt], awh, vh2[0], vh2[1]);
                MMA16816(o[nt], awh, vl2[0], vl2[1]);
                MMA16816(o[nt], awl, vh2[0], vh2[1]);
            }
        }
    }

    // ---- write O (one 1024-col row per head) as bf16 hi/lo ----
    const size_t orow = (size_t)(n * 1024 + h * 64 + a) * 1024;
    #pragma unroll
    for (int nt = 0; nt < 8; ++nt) {
        int c0 = nt * 8 + 2 * lc;
        __nv_bfloat16 h0, h1, l0, l1;
        split_bf16(o[nt][0], h0, l0); split_bf16(o[nt][1], h1, l1);
        *(__nv_bfloat162*)(Oh + orow + lr * 64 + c0) = __nv_bfloat162(h0, h1);
        *(__nv_bfloat162*)(Ol + orow + lr * 64 + c0) = __nv_bfloat162(l0, l1);
        split_bf16(o[nt][2], h0, l0); split_bf16(o[nt][3], h1, l1);
        *(__nv_bfloat162*)(Oh + orow + (lr + 8) * 64 + c0) = __nv_bfloat162(h0, h1);
        *(__nv_bfloat162*)(Ol + orow + (lr + 8) * 64 + c0) = __nv_bfloat162(l0, l1);
    }
}

// ---------------- fused residual + LayerNorm (+ optional hi/lo emit) ---------
__global__ __launch_bounds__(256) void ln_kernel(
    const float* __restrict__ A, const float* __restrict__ R,
    const float* __restrict__ g, const float* __restrict__ bta,
    float* __restrict__ out, __nv_bfloat16* __restrict__ Xh,
    __nv_bfloat16* __restrict__ Xl)
{
    __shared__ float red[16];
    const int row = blockIdx.x;
    const int tid = threadIdx.x;

    float4 v = ((const float4*)(A + (size_t)row * 1024))[tid];
    float4 r = ((const float4*)(R + (size_t)row * 1024))[tid];
    v.x += r.x; v.y += r.y; v.z += r.z; v.w += r.w;

    float s  = v.x + v.y + v.z + v.w;
    float sq = v.x * v.x + v.y * v.y + v.z * v.z + v.w * v.w;
    #pragma unroll
    for (int o = 16; o > 0; o >>= 1) {
        s  += __shfl_xor_sync(0xffffffffu, s,  o);
        sq += __shfl_xor_sync(0xffffffffu, sq, o);
    }
    if ((tid & 31) == 0) { red[tid >> 5] = s; red[8 + (tid >> 5)] = sq; }
    __syncthreads();
    float S = 0.f, SQ = 0.f;
    #pragma unroll
    for (int w = 0; w < 8; ++w) { S += red[w]; SQ += red[8 + w]; }

    const float mean = S * (1.f / 1024.f);
    const float var  = SQ * (1.f / 1024.f) - mean * mean;
    const float rstd = rsqrtf(var + 1e-5f);

    float4 gv = ((const float4*)g)[tid];
    float4 bv = ((const float4*)bta)[tid];
    float4 o;
    o.x = (v.x - mean) * rstd * gv.x + bv.x;
    o.y = (v.y - mean) * rstd * gv.y + bv.y;
    o.z = (v.z - mean) * rstd * gv.z + bv.z;
    o.w = (v.w - mean) * rstd * gv.w + bv.w;
    ((float4*)(out + (size_t)row * 1024))[tid] = o;

    if (Xh) {
        __nv_bfloat16 h0, h1, h2, h3, l0, l1, l2, l3;
        split_bf16(o.x, h0, l0); split_bf16(o.y, h1, l1);
        split_bf16(o.z, h2, l2); split_bf16(o.w, h3, l3);
        size_t oo = (size_t)row * 1024 + tid * 4;
        *(__nv_bfloat162*)(Xh + oo)     = __nv_bfloat162(h0, h1);
        *(__nv_bfloat162*)(Xh + oo + 2) = __nv_bfloat162(h2, h3);
        *(__nv_bfloat162*)(Xl + oo)     = __nv_bfloat162(l0, l1);
        *(__nv_bfloat162*)(Xl + oo + 2) = __nv_bfloat162(l2, l3);
    }
}

// ---------------- launch ------------------------------------------------------
extern "C" void kernel_launch(void* const* d_in, const int* in_sizes, int n_in,
                              void* d_out, int out_size)
{
    const float* x  = (const float*)d_in[0];
    const float* Wq = (const float*)d_in[1];
    const float* bq = (const float*)d_in[2];
    const float* Wk = (const float*)d_in[3];
    const float* bk = (const float*)d_in[4];
    const float* Wv = (const float*)d_in[5];
    const float* bv = (const float*)d_in[6];
    const float* Wo = (const float*)d_in[7];
    const float* bo = (const float*)d_in[8];
    const float* g1 = (const float*)d_in[9];
    const float* b1 = (const float*)d_in[10];
    const float* W1 = (const float*)d_in[11];
    const float* c1 = (const float*)d_in[12];
    const float* W2 = (const float*)d_in[13];
    const float* c2 = (const float*)d_in[14];
    const float* g2 = (const float*)d_in[15];
    const float* b2 = (const float*)d_in[16];
    float* out = (float*)d_out;

    float *pX1, *pF, *pbqkv;
    __nv_bfloat16 *pAh, *pAl, *pHh, *pHl, *pBh, *pBl;
    cudaGetSymbolAddress((void**)&pX1,  g_X1);
    cudaGetSymbolAddress((void**)&pF,   g_F);
    cudaGetSymbolAddress((void**)&pbqkv,g_bqkv);
    cudaGetSymbolAddress((void**)&pAh,  g_Ah);
    cudaGetSymbolAddress((void**)&pAl,  g_Al);
    cudaGetSymbolAddress((void**)&pHh,  g_Hh);
    cudaGetSymbolAddress((void**)&pHl,  g_Hl);
    cudaGetSymbolAddress((void**)&pBh,  g_Bh);
    cudaGetSymbolAddress((void**)&pBl,  g_Bl);

    cudaFuncSetAttribute(attn_kernel, cudaFuncAttributeMaxDynamicSharedMemorySize, ATTN_SMEM);
    cudaFuncSetAttribute(gemm_tc_kernel, cudaFuncAttributeMaxDynamicSharedMemorySize, G_SMEM);

    dim3 blk(256);
    dim3 t32(32, 8);
    const int n4_1 = NTOK * HID / 4;
    dim3 gs1((n4_1 + 255) / 256);
    dim3 tg11(HID / 32, HID / 32);
    dim3 tg14(4 * HID / 32, HID / 32);
    dim3 tg41(HID / 32, 4 * HID / 32);
    dim3 ggqkv(3 * HID / 128, NTOK / 128);
    dim3 gg1(HID / 128, NTOK / 128);
    dim3 gg4(4 * HID / 128, NTOK / 128);

    // ---- QKV: split x, pack W_{q,k,v}^T, one N=3072 GEMM -> bf16 hi/lo ----
    split_kernel<<<gs1, blk>>>(x, pAh, pAl, n4_1);
    tsplit_kernel<<<tg11, t32>>>(Wq, pBh,               pBl,               HID, HID);
    tsplit_kernel<<<tg11, t32>>>(Wk, pBh + 1024 * 1024, pBl + 1024 * 1024, HID, HID);
    tsplit_kernel<<<tg11, t32>>>(Wv, pBh + 2048 * 1024, pBl + 2048 * 1024, HID, HID);
    cudaMemcpyAsync(pbqkv,        bq, HID * 4, cudaMemcpyDeviceToDevice, 0);
    cudaMemcpyAsync(pbqkv + 1024, bk, HID * 4, cudaMemcpyDeviceToDevice, 0);
    cudaMemcpyAsync(pbqkv + 2048, bv, HID * 4, cudaMemcpyDeviceToDevice, 0);
    gemm_tc_kernel<<<ggqkv, blk, G_SMEM>>>(pAh, pAl, pBh, pBl, pbqkv,
                                           nullptr, pHh, pHl,
                                           NTOK, 3 * HID, HID, 0);

    // ---- tensor-core attention; emits O hi/lo ----
    attn_kernel<<<dim3(64, 4), 512, ATTN_SMEM>>>(pHh, pHl, pAh, pAl);

    // ---- output projection, residual + LN1 (emits X1 fp32 + hi/lo) ----
    tsplit_kernel<<<tg11, t32>>>(Wo, pBh, pBl, HID, HID);
    gemm_tc_kernel<<<gg1, blk, G_SMEM>>>(pAh, pAl, pBh, pBl, bo,
                                         pF, nullptr, nullptr,
                                         NTOK, HID, HID, 0);
    ln_kernel<<<NTOK, blk>>>(pF, x, g1, b1, pX1, pAh, pAl);

    // ---- FFN ----
    tsplit_kernel<<<tg14, t32>>>(W1, pBh, pBl, HID, 4 * HID);
    gemm_tc_kernel<<<gg4, blk, G_SMEM>>>(pAh, pAl, pBh, pBl, c1,
                                         nullptr, pHh, pHl,
                                         NTOK, 4 * HID, HID, 1);
    tsplit_kernel<<<tg41, t32>>>(W2, pBh, pBl, 4 * HID, HID);
    gemm_tc_kernel<<<gg1, blk, G_SMEM>>>(pHh, pHl, pBh, pBl, c2,
                                         pF, nullptr, nullptr,
                                         NTOK, HID, 4 * HID, 0);

    // ---- residual + LN2 -> output ----
    ln_kernel<<<NTOK, blk>>>(pF, pX1, g2, b2, out, nullptr, nullptr);
}

// round 7
// speedup vs baseline: 2.1571x; 1.6081x over previous
#include <cuda_runtime.h>
#include <cuda_fp16.h>
#include <stdint.h>
#include <math.h>

// ---------------- scratch buffers (static device memory, no allocs) ----------
#define NTOK 4096              // 4 * 1024 rows
#define HID  1024
__device__ float g_X1 [NTOK * HID];
__device__ float g_F  [NTOK * HID];
__device__ float g_bqkv[3 * HID];
__device__ __half g_Ah[NTOK * HID];       // activations hi (x / O / X1)
__device__ __half g_Al[NTOK * HID];       // activations lo
__device__ __half g_Hh[NTOK * 4 * HID];   // QKV hi, later FF hidden hi
__device__ __half g_Hl[NTOK * 4 * HID];   // QKV lo, later FF hidden lo
__device__ __half g_Bh[4 * HID * HID];    // transposed weights (single fp16)

// ---------------- PTX helpers (arch-neutral only) -----------------------------
__device__ __forceinline__ uint32_t smem_u32(const void* p) {
    uint32_t a;
    asm("{ .reg .u64 t; cvta.to.shared.u64 t, %1; cvt.u32.u64 %0, t; }"
        : "=r"(a) : "l"(p));
    return a;
}
#define CP_ASYNC16(s, g) \
    asm volatile("cp.async.cg.shared.global [%0], [%1], 16;" :: "r"(s), "l"(g))
#define CP_COMMIT() asm volatile("cp.async.commit_group;" ::: "memory")
#define CP_WAIT(n)  asm volatile("cp.async.wait_group %0;" :: "n"(n) : "memory")
#define LDSM_X4(r, addr) \
    asm volatile("ldmatrix.sync.aligned.m8n8.x4.shared.b16 {%0,%1,%2,%3}, [%4];" \
        : "=r"((r)[0]), "=r"((r)[1]), "=r"((r)[2]), "=r"((r)[3]) : "r"(addr))
#define LDSM_X2(r, addr) \
    asm volatile("ldmatrix.sync.aligned.m8n8.x2.shared.b16 {%0,%1}, [%2];" \
        : "=r"((r)[0]), "=r"((r)[1]) : "r"(addr))
#define LDSM_X2T(r, addr) \
    asm volatile("ldmatrix.sync.aligned.m8n8.x2.trans.shared.b16 {%0,%1}, [%2];" \
        : "=r"((r)[0]), "=r"((r)[1]) : "r"(addr))
#define MMAF16(c, a, b0, b1) \
    asm volatile("mma.sync.aligned.m16n8k16.row.col.f32.f16.f16.f32 " \
        "{%0,%1,%2,%3}, {%4,%5,%6,%7}, {%8,%9}, {%0,%1,%2,%3};" \
        : "+f"((c)[0]), "+f"((c)[1]), "+f"((c)[2]), "+f"((c)[3]) \
        : "r"((a)[0]), "r"((a)[1]), "r"((a)[2]), "r"((a)[3]), "r"(b0), "r"(b1))

__device__ __forceinline__ void split_h(float v, __half& h, __half& l) {
    h = __float2half_rn(v);
    l = __float2half_rn(v - __half2float(h));
}
__device__ __forceinline__ uint32_t pack_h2(__half x, __half y) {
    __half2 p = __halves2half2(x, y);
    return *reinterpret_cast<uint32_t*>(&p);
}

// ---------------- conversion kernels -----------------------------------------
__global__ __launch_bounds__(256) void split_kernel(
    const float* __restrict__ A, __half* __restrict__ H,
    __half* __restrict__ L, int n4)
{
    int i = blockIdx.x * 256 + threadIdx.x;
    if (i >= n4) return;
    float4 v = ((const float4*)A)[i];
    __half h0, h1, h2, h3, l0, l1, l2, l3;
    split_h(v.x, h0, l0); split_h(v.y, h1, l1);
    split_h(v.z, h2, l2); split_h(v.w, h3, l3);
    ((__half2*)H)[i * 2 + 0] = __halves2half2(h0, h1);
    ((__half2*)H)[i * 2 + 1] = __halves2half2(h2, h3);
    ((__half2*)L)[i * 2 + 0] = __halves2half2(l0, l1);
    ((__half2*)L)[i * 2 + 1] = __halves2half2(l2, l3);
}

// transpose + round: W [K x N] fp32 -> H [N x K] fp16 (single)
__global__ __launch_bounds__(256) void tsplit_kernel(
    const float* __restrict__ W, __half* __restrict__ H, int K, int N)
{
    __shared__ float t[32][33];
    const int tx = threadIdx.x, ty = threadIdx.y;
    const int bk = blockIdx.y * 32, bn = blockIdx.x * 32;
    #pragma unroll
    for (int j = 0; j < 4; ++j)
        t[ty + j * 8][tx] = W[(size_t)(bk + ty + j * 8) * N + bn + tx];
    __syncthreads();
    #pragma unroll
    for (int j = 0; j < 4; ++j) {
        int r = ty + j * 8;
        H[(size_t)(bn + r) * K + bk + tx] = __float2half_rn(t[tx][r]);
    }
}

// ---------------- fp16 2-term split tensor-core GEMM -------------------------
// C = act((Ah+Al) @ Bh^T + bias). Tile 128x128, BK=32, 8 warps, 2 MMAs/tile.
#define G_PART  8192
#define G_STAGE (3 * G_PART)
#define G_SMEM  (2 * G_STAGE)

__global__ __launch_bounds__(256) void gemm_tc_kernel(
    const __half* __restrict__ Ah, const __half* __restrict__ Al,
    const __half* __restrict__ Bh,
    const float* __restrict__ bias,
    float* __restrict__ Cf, __half* __restrict__ Ch, __half* __restrict__ Cl,
    int M, int N, int K, int act)
{
    extern __shared__ char smem[];
    const uint32_t sb = smem_u32(smem);
    const int tid = threadIdx.x;
    const int wid = tid >> 5, lane = tid & 31;
    const int warp_m = wid >> 2, warp_n = wid & 3;
    const int bm = blockIdx.y * 128, bn = blockIdx.x * 128;

    float acc[4][4][4];
    #pragma unroll
    for (int i = 0; i < 4; ++i)
        #pragma unroll
        for (int j = 0; j < 4; ++j)
            #pragma unroll
            for (int r = 0; r < 4; ++r) acc[i][j][r] = 0.f;

    const int swz = (lane & 7) >> 1;
    const int rA = warp_m * 64 + ((lane >> 3) & 1) * 8 + (lane & 7);
    const int kA = lane >> 4;
    const int rB = warp_n * 32 + (lane >> 4) * 8 + (lane & 7);
    const int kB = (lane >> 3) & 1;

    const int nst = K >> 5;

    auto load_stage = [&](int j) {
        const uint32_t st = sb + (uint32_t)(j & 1) * G_STAGE;
        const int kc = j * 32;
        #pragma unroll
        for (int t = 0; t < 2; ++t) {
            int idx = tid + t * 256;
            int row = idx >> 2, ch = idx & 3;
            uint32_t so = (uint32_t)row * 64 + (uint32_t)((ch ^ ((row >> 1) & 3)) << 4);
            size_t ga = (size_t)(bm + row) * K + kc + ch * 8;
            size_t gb = (size_t)(bn + row) * K + kc + ch * 8;
            CP_ASYNC16(st + 0 * G_PART + so, Ah + ga);
            CP_ASYNC16(st + 1 * G_PART + so, Al + ga);
            CP_ASYNC16(st + 2 * G_PART + so, Bh + gb);
        }
        CP_COMMIT();
    };

    load_stage(0);

    for (int j = 0; j < nst; ++j) {
        if (j + 1 < nst) { load_stage(j + 1); CP_WAIT(1); }
        else             { CP_WAIT(0); }
        __syncthreads();

        const uint32_t st = sb + (uint32_t)(j & 1) * G_STAGE;
        #pragma unroll
        for (int ks = 0; ks < 2; ++ks) {
            uint32_t ah[4][4], al[4][4], bh[2][4];
            #pragma unroll
            for (int mt = 0; mt < 4; ++mt) {
                uint32_t ao = (uint32_t)(rA + mt * 16) * 64
                            + (uint32_t)(((ks * 2 + kA) ^ swz) << 4);
                LDSM_X4(ah[mt], st + 0 * G_PART + ao);
                LDSM_X4(al[mt], st + 1 * G_PART + ao);
            }
            #pragma unroll
            for (int np = 0; np < 2; ++np) {
                uint32_t bo = (uint32_t)(rB + np * 16) * 64
                            + (uint32_t)(((ks * 2 + kB) ^ swz) << 4);
                LDSM_X4(bh[np], st + 2 * G_PART + bo);
            }
            #pragma unroll
            for (int mt = 0; mt < 4; ++mt)
                #pragma unroll
                for (int nt = 0; nt < 4; ++nt) {
                    const uint32_t* bhp = &bh[nt >> 1][(nt & 1) * 2];
                    MMAF16(acc[mt][nt], ah[mt], bhp[0], bhp[1]);
                    MMAF16(acc[mt][nt], al[mt], bhp[0], bhp[1]);
                }
        }
        __syncthreads();
    }

    // epilogue
    #pragma unroll
    for (int mt = 0; mt < 4; ++mt)
        #pragma unroll
        for (int nt = 0; nt < 4; ++nt) {
            int row0 = bm + warp_m * 64 + mt * 16 + (lane >> 2);
            int col  = bn + warp_n * 32 + nt * 8 + (lane & 3) * 2;
            float b0 = bias[col], b1 = bias[col + 1];
            float v[4];
            v[0] = acc[mt][nt][0] + b0;
            v[1] = acc[mt][nt][1] + b1;
            v[2] = acc[mt][nt][2] + b0;
            v[3] = acc[mt][nt][3] + b1;
            if (act) {
                #pragma unroll
                for (int r = 0; r < 4; ++r)
                    v[r] = 0.5f * v[r] * (1.f + erff(v[r] * 0.70710678118654752f));
            }
            if (Cf) {
                *(float2*)&Cf[(size_t)row0 * N + col]       = make_float2(v[0], v[1]);
                *(float2*)&Cf[(size_t)(row0 + 8) * N + col] = make_float2(v[2], v[3]);
            } else {
                __half h0, h1, l0, l1;
                split_h(v[0], h0, l0); split_h(v[1], h1, l1);
                *(__half2*)&Ch[(size_t)row0 * N + col] = __halves2half2(h0, h1);
                *(__half2*)&Cl[(size_t)row0 * N + col] = __halves2half2(l0, l1);
                split_h(v[2], h0, l0); split_h(v[3], h1, l1);
                *(__half2*)&Ch[(size_t)(row0 + 8) * N + col] = __halves2half2(h0, h1);
                *(__half2*)&Cl[(size_t)(row0 + 8) * N + col] = __halves2half2(l0, l1);
            }
        }
}

// ---------------- tensor-core attention with head-axis softmax ----------------
// QKV packed fp16 hi/lo [4096][3072]. Per block (a, n): 16 warps, warp = head.
// Q split (hi+lo), K/V single fp16 -> 2 MMAs per step. K+V double-buffered.
#define SCW(hh, b, p) ((hh) * 290 + (b) * 18 + (p))
#define AT_STG 65536                 // K (32KB) + V (32KB) per stage
#define ATTN_SMEM (2 * AT_STG + 290 * 16 * 4)

__global__ __launch_bounds__(512, 1) void attn_kernel(
    const __half* __restrict__ Ph, const __half* __restrict__ Pl,
    __half* __restrict__ Oh, __half* __restrict__ Ol)
{
    extern __shared__ char smem[];
    const uint32_t sb = smem_u32(smem);
    float* sc = (float*)(smem + 2 * AT_STG);

    const int tid = threadIdx.x, lane = tid & 31, h = tid >> 5;
    const int a = blockIdx.x, n = blockIdx.y;
    const int lr = lane >> 2, lc = lane & 3;

    // ---- stage Q (hi into [0,32K), lo into [32K,64K)), extract fragments ----
    {
        #pragma unroll
        for (int t = 0; t < 4; ++t) {
            int f = tid + t * 512;
            int hh = f >> 7, bp = (f >> 3) & 15, c = f & 7;
            uint32_t dst = (uint32_t)hh * 2048 + bp * 128 + ((c ^ (bp & 7)) << 4);
            size_t src = (size_t)(n * 1024 + hh * 64 + a) * 3072 + bp * 64 + c * 8;
            CP_ASYNC16(sb + dst,         Ph + src);
            CP_ASYNC16(sb + 32768 + dst, Pl + src);
        }
        CP_COMMIT(); CP_WAIT(0); __syncthreads();
    }
    uint32_t qh[4][4], ql[4][4];
    {
        int b = lane & 15, cs = lane >> 4;
        #pragma unroll
        for (int ks = 0; ks < 4; ++ks) {
            uint32_t ad = (uint32_t)h * 2048 + b * 128
                        + (((ks * 2 + cs) ^ (b & 7)) << 4);
            LDSM_X4(qh[ks], sb + ad);
            LDSM_X4(ql[ks], sb + 32768 + ad);
        }
    }
    __syncthreads();   // everyone done reading Q before KV overwrites stage 0

    auto stageKV = [&](int ap, int s) {
        uint32_t base = sb + (uint32_t)s * AT_STG;
        #pragma unroll
        for (int t = 0; t < 4; ++t) {
            int f = tid + t * 512;
            int hh = f >> 7, bp = (f >> 3) & 15, c = f & 7;
            uint32_t dst = (uint32_t)hh * 2048 + bp * 128 + ((c ^ (bp & 7)) << 4);
            size_t row = (size_t)(n * 1024 + hh * 64 + ap) * 3072;
            CP_ASYNC16(base + dst,         Ph + row + 1024 + bp * 64 + c * 8);
            CP_ASYNC16(base + 32768 + dst, Ph + row + 2048 + bp * 64 + c * 8);
        }
        CP_COMMIT();
    };

    float o[8][4];
    #pragma unroll
    for (int nt = 0; nt < 8; ++nt)
        #pragma unroll
        for (int r = 0; r < 4; ++r) o[nt][r] = 0.f;

    stageKV(0, 0);
    for (int ap = 0; ap < 64; ++ap) {
        const int s = ap & 1;
        if (ap + 1 < 64) { stageKV(ap + 1, s ^ 1); CP_WAIT(1); }
        else             { CP_WAIT(0); }
        __syncthreads();

        const uint32_t kb = sb + (uint32_t)s * AT_STG;
        const uint32_t vb = kb + 32768;

        // ---- scores: S = (Qh+Ql) K^T ----
        float sv[2][4];
        #pragma unroll
        for (int nt = 0; nt < 2; ++nt)
            #pragma unroll
            for (int r = 0; r < 4; ++r) sv[nt][r] = 0.f;
        {
            int bpr = lane & 7, khalf = (lane >> 3) & 1;
            #pragma unroll
            for (int ks = 0; ks < 4; ++ks)
                #pragma unroll
                for (int nt = 0; nt < 2; ++nt) {
                    int row = nt * 8 + bpr;
                    uint32_t ad = (uint32_t)h * 2048 + row * 128
                                + (((ks * 2 + khalf) ^ (row & 7)) << 4);
                    uint32_t k2[2];
                    LDSM_X2(k2, kb + ad);
                    MMAF16(sv[nt], qh[ks], k2[0], k2[1]);
                    MMAF16(sv[nt], ql[ks], k2[0], k2[1]);
                }
        }
        #pragma unroll
        for (int nt = 0; nt < 2; ++nt) {
            int c0 = nt * 8 + 2 * lc;
            sc[SCW(h, lr,     c0)]     = sv[nt][0] * 0.03125f;
            sc[SCW(h, lr,     c0 + 1)] = sv[nt][1] * 0.03125f;
            sc[SCW(h, lr + 8, c0)]     = sv[nt][2] * 0.03125f;
            sc[SCW(h, lr + 8, c0 + 1)] = sv[nt][3] * 0.03125f;
        }
        __syncthreads();

        // ---- head-softmax: thread p owns (b = p>>4, b' = p&15) ----
        if (tid < 256) {
            const int pb = tid >> 4, pbp = tid & 15;
            float m = -1e30f;
            #pragma unroll
            for (int hh = 0; hh < 16; ++hh) m = fmaxf(m, sc[SCW(hh, pb, pbp)]);
            float ssum = 0.f;
            #pragma unroll
            for (int hh = 0; hh < 16; ++hh) {
                float e = __expf(sc[SCW(hh, pb, pbp)] - m);
                ssum += e;
                sc[SCW(hh, pb, pbp)] = e;
            }
            float inv = 1.f / ssum;
            #pragma unroll
            for (int hh = 0; hh < 16; ++hh) sc[SCW(hh, pb, pbp)] *= inv;
        }
        __syncthreads();

        // ---- W fragments (fp16 hi/lo of the exact fp32 weights) ----
        uint32_t awh[4], awl[4];
        {
            float wv[8];
            wv[0] = sc[SCW(h, lr,     2 * lc)];
            wv[1] = sc[SCW(h, lr,     2 * lc + 1)];
            wv[2] = sc[SCW(h, lr + 8, 2 * lc)];
            wv[3] = sc[SCW(h, lr + 8, 2 * lc + 1)];
            wv[4] = sc[SCW(h, lr,     2 * lc + 8)];
            wv[5] = sc[SCW(h, lr,     2 * lc + 9)];
            wv[6] = sc[SCW(h, lr + 8, 2 * lc + 8)];
            wv[7] = sc[SCW(h, lr + 8, 2 * lc + 9)];
            #pragma unroll
            for (int i = 0; i < 4; ++i) {
                __half h0, h1, l0, l1;
                split_h(wv[2 * i],     h0, l0);
                split_h(wv[2 * i + 1], h1, l1);
                awh[i] = pack_h2(h0, h1);
                awl[i] = pack_h2(l0, l1);
            }
        }

        // ---- AV: O += (Wh+Wl) V (V via ldmatrix.trans) ----
        {
            int bp = lane & 15;
            #pragma unroll
            for (int nt = 0; nt < 8; ++nt) {
                uint32_t ad = (uint32_t)h * 2048 + bp * 128
                            + ((nt ^ (bp & 7)) << 4);
                uint32_t v2[2];
                LDSM_X2T(v2, vb + ad);
                MMAF16(o[nt], awh, v2[0], v2[1]);
                MMAF16(o[nt], awl, v2[0], v2[1]);
            }
        }
        __syncthreads();   // all reads of buffer s / sc done before next overwrite
    }

    // ---- write O (one 1024-col row per head) as fp16 hi/lo ----
    const size_t orow = (size_t)(n * 1024 + h * 64 + a) * 1024;
    #pragma unroll
    for (int nt = 0; nt < 8; ++nt) {
        int c0 = nt * 8 + 2 * lc;
        __half h0, h1, l0, l1;
        split_h(o[nt][0], h0, l0); split_h(o[nt][1], h1, l1);
        *(__half2*)(Oh + orow + lr * 64 + c0) = __halves2half2(h0, h1);
        *(__half2*)(Ol + orow + lr * 64 + c0) = __halves2half2(l0, l1);
        split_h(o[nt][2], h0, l0); split_h(o[nt][3], h1, l1);
        *(__half2*)(Oh + orow + (lr + 8) * 64 + c0) = __halves2half2(h0, h1);
        *(__half2*)(Ol + orow + (lr + 8) * 64 + c0) = __halves2half2(l0, l1);
    }
}

// ---------------- fused residual + LayerNorm (+ optional hi/lo emit) ---------
__global__ __launch_bounds__(256) void ln_kernel(
    const float* __restrict__ A, const float* __restrict__ R,
    const float* __restrict__ g, const float* __restrict__ bta,
    float* __restrict__ out, __half* __restrict__ Xh, __half* __restrict__ Xl)
{
    __shared__ float red[16];
    const int row = blockIdx.x;
    const int tid = threadIdx.x;

    float4 v = ((const float4*)(A + (size_t)row * 1024))[tid];
    float4 r = ((const float4*)(R + (size_t)row * 1024))[tid];
    v.x += r.x; v.y += r.y; v.z += r.z; v.w += r.w;

    float s  = v.x + v.y + v.z + v.w;
    float sq = v.x * v.x + v.y * v.y + v.z * v.z + v.w * v.w;
    #pragma unroll
    for (int o = 16; o > 0; o >>= 1) {
        s  += __shfl_xor_sync(0xffffffffu, s,  o);
        sq += __shfl_xor_sync(0xffffffffu, sq, o);
    }
    if ((tid & 31) == 0) { red[tid >> 5] = s; red[8 + (tid >> 5)] = sq; }
    __syncthreads();
    float S = 0.f, SQ = 0.f;
    #pragma unroll
    for (int w = 0; w < 8; ++w) { S += red[w]; SQ += red[8 + w]; }

    const float mean = S * (1.f / 1024.f);
    const float var  = SQ * (1.f / 1024.f) - mean * mean;
    const float rstd = rsqrtf(var + 1e-5f);

    float4 gv = ((const float4*)g)[tid];
    float4 bv = ((const float4*)bta)[tid];
    float4 o;
    o.x = (v.x - mean) * rstd * gv.x + bv.x;
    o.y = (v.y - mean) * rstd * gv.y + bv.y;
    o.z = (v.z - mean) * rstd * gv.z + bv.z;
    o.w = (v.w - mean) * rstd * gv.w + bv.w;
    ((float4*)(out + (size_t)row * 1024))[tid] = o;

    if (Xh) {
        __half h0, h1, h2, h3, l0, l1, l2, l3;
        split_h(o.x, h0, l0); split_h(o.y, h1, l1);
        split_h(o.z, h2, l2); split_h(o.w, h3, l3);
        size_t oo = (size_t)row * 1024 + tid * 4;
        *(__half2*)(Xh + oo)     = __halves2half2(h0, h1);
        *(__half2*)(Xh + oo + 2) = __halves2half2(h2, h3);
        *(__half2*)(Xl + oo)     = __halves2half2(l0, l1);
        *(__half2*)(Xl + oo + 2) = __halves2half2(l2, l3);
    }
}

// ---------------- launch ------------------------------------------------------
extern "C" void kernel_launch(void* const* d_in, const int* in_sizes, int n_in,
                              void* d_out, int out_size)
{
    const float* x  = (const float*)d_in[0];
    const float* Wq = (const float*)d_in[1];
    const float* bq = (const float*)d_in[2];
    const float* Wk = (const float*)d_in[3];
    const float* bk = (const float*)d_in[4];
    const float* Wv = (const float*)d_in[5];
    const float* bv = (const float*)d_in[6];
    const float* Wo = (const float*)d_in[7];
    const float* bo = (const float*)d_in[8];
    const float* g1 = (const float*)d_in[9];
    const float* b1 = (const float*)d_in[10];
    const float* W1 = (const float*)d_in[11];
    const float* c1 = (const float*)d_in[12];
    const float* W2 = (const float*)d_in[13];
    const float* c2 = (const float*)d_in[14];
    const float* g2 = (const float*)d_in[15];
    const float* b2 = (const float*)d_in[16];
    float* out = (float*)d_out;

    float *pX1, *pF, *pbqkv;
    __half *pAh, *pAl, *pHh, *pHl, *pBh;
    cudaGetSymbolAddress((void**)&pX1,  g_X1);
    cudaGetSymbolAddress((void**)&pF,   g_F);
    cudaGetSymbolAddress((void**)&pbqkv,g_bqkv);
    cudaGetSymbolAddress((void**)&pAh,  g_Ah);
    cudaGetSymbolAddress((void**)&pAl,  g_Al);
    cudaGetSymbolAddress((void**)&pHh,  g_Hh);
    cudaGetSymbolAddress((void**)&pHl,  g_Hl);
    cudaGetSymbolAddress((void**)&pBh,  g_Bh);

    cudaFuncSetAttribute(attn_kernel, cudaFuncAttributeMaxDynamicSharedMemorySize, ATTN_SMEM);
    cudaFuncSetAttribute(gemm_tc_kernel, cudaFuncAttributeMaxDynamicSharedMemorySize, G_SMEM);

    dim3 blk(256);
    dim3 t32(32, 8);
    const int n4_1 = NTOK * HID / 4;
    dim3 gs1((n4_1 + 255) / 256);
    dim3 tg11(HID / 32, HID / 32);
    dim3 tg14(4 * HID / 32, HID / 32);
    dim3 tg41(HID / 32, 4 * HID / 32);
    dim3 ggqkv(3 * HID / 128, NTOK / 128);
    dim3 gg1(HID / 128, NTOK / 128);
    dim3 gg4(4 * HID / 128, NTOK / 128);

    // ---- QKV: split x (hi/lo), round W_{q,k,v}^T, one N=3072 GEMM ----
    split_kernel<<<gs1, blk>>>(x, pAh, pAl, n4_1);
    tsplit_kernel<<<tg11, t32>>>(Wq, pBh,               HID, HID);
    tsplit_kernel<<<tg11, t32>>>(Wk, pBh + 1024 * 1024, HID, HID);
    tsplit_kernel<<<tg11, t32>>>(Wv, pBh + 2048 * 1024, HID, HID);
    cudaMemcpyAsync(pbqkv,        bq, HID * 4, cudaMemcpyDeviceToDevice, 0);
    cudaMemcpyAsync(pbqkv + 1024, bk, HID * 4, cudaMemcpyDeviceToDevice, 0);
    cudaMemcpyAsync(pbqkv + 2048, bv, HID * 4, cudaMemcpyDeviceToDevice, 0);
    gemm_tc_kernel<<<ggqkv, blk, G_SMEM>>>(pAh, pAl, pBh, pbqkv,
                                           nullptr, pHh, pHl,
                                           NTOK, 3 * HID, HID, 0);

    // ---- tensor-core attention; emits O hi/lo ----
    attn_kernel<<<dim3(64, 4), 512, ATTN_SMEM>>>(pHh, pHl, pAh, pAl);

    // ---- output projection, residual + LN1 (emits X1 fp32 + hi/lo) ----
    tsplit_kernel<<<tg11, t32>>>(Wo, pBh, HID, HID);
    gemm_tc_kernel<<<gg1, blk, G_SMEM>>>(pAh, pAl, pBh, bo,
                                         pF, nullptr, nullptr,
                                         NTOK, HID, HID, 0);
    ln_kernel<<<NTOK, blk>>>(pF, x, g1, b1, pX1, pAh, pAl);

    // ---- FFN ----
    tsplit_kernel<<<tg14, t32>>>(W1, pBh, HID, 4 * HID);
    gemm_tc_kernel<<<gg4, blk, G_SMEM>>>(pAh, pAl, pBh, c1,
                                         nullptr, pHh, pHl,
                                         NTOK, 4 * HID, HID, 1);
    tsplit_kernel<<<tg41, t32>>>(W2, pBh, 4 * HID, HID);
    gemm_tc_kernel<<<gg1, blk, G_SMEM>>>(pHh, pHl, pBh, c2,
                                         pF, nullptr, nullptr,
                                         NTOK, HID, 4 * HID, 0);

    // ---- residual + LN2 -> output ----
    ln_kernel<<<NTOK, blk>>>(pF, pX1, g2, b2, out, nullptr, nullptr);
}

// round 8
// speedup vs baseline: 3.0121x; 1.3964x over previous
#include <cuda_runtime.h>
#include <cuda_fp16.h>
#include <stdint.h>
#include <math.h>

// ---------------- scratch buffers (static device memory, no allocs) ----------
#define NTOK 4096              // 4 * 1024 rows
#define HID  1024
__device__ float g_X1 [NTOK * HID];
__device__ float g_F  [NTOK * HID];
__device__ float g_bqkv[3 * HID];
__device__ __half g_Ah[NTOK * HID];       // activations fp16 (x / O / X1)
__device__ __half g_Hh[NTOK * 4 * HID];   // QKV hi, later FF hidden
__device__ __half g_Hl[NTOK * HID];       // QKV lo (Q section only)
__device__ __half g_Bh[4 * HID * HID];    // transposed weights fp16

// ---------------- PTX helpers (arch-neutral only) -----------------------------
__device__ __forceinline__ uint32_t smem_u32(const void* p) {
    uint32_t a;
    asm("{ .reg .u64 t; cvta.to.shared.u64 t, %1; cvt.u32.u64 %0, t; }"
        : "=r"(a) : "l"(p));
    return a;
}
#define CP_ASYNC16(s, g) \
    asm volatile("cp.async.cg.shared.global [%0], [%1], 16;" :: "r"(s), "l"(g))
#define CP_COMMIT() asm volatile("cp.async.commit_group;" ::: "memory")
#define CP_WAIT(n)  asm volatile("cp.async.wait_group %0;" :: "n"(n) : "memory")
#define LDSM_X4(r, addr) \
    asm volatile("ldmatrix.sync.aligned.m8n8.x4.shared.b16 {%0,%1,%2,%3}, [%4];" \
        : "=r"((r)[0]), "=r"((r)[1]), "=r"((r)[2]), "=r"((r)[3]) : "r"(addr))
#define LDSM_X2(r, addr) \
    asm volatile("ldmatrix.sync.aligned.m8n8.x2.shared.b16 {%0,%1}, [%2];" \
        : "=r"((r)[0]), "=r"((r)[1]) : "r"(addr))
#define LDSM_X2T(r, addr) \
    asm volatile("ldmatrix.sync.aligned.m8n8.x2.trans.shared.b16 {%0,%1}, [%2];" \
        : "=r"((r)[0]), "=r"((r)[1]) : "r"(addr))
#define MMAF16(c, a, b0, b1) \
    asm volatile("mma.sync.aligned.m16n8k16.row.col.f32.f16.f16.f32 " \
        "{%0,%1,%2,%3}, {%4,%5,%6,%7}, {%8,%9}, {%0,%1,%2,%3};" \
        : "+f"((c)[0]), "+f"((c)[1]), "+f"((c)[2]), "+f"((c)[3]) \
        : "r"((a)[0]), "r"((a)[1]), "r"((a)[2]), "r"((a)[3]), "r"(b0), "r"(b1))

__device__ __forceinline__ void split_h(float v, __half& h, __half& l) {
    h = __float2half_rn(v);
    l = __float2half_rn(v - __half2float(h));
}
__device__ __forceinline__ uint32_t pack_h2(__half x, __half y) {
    __half2 p = __halves2half2(x, y);
    return *reinterpret_cast<uint32_t*>(&p);
}

// ---------------- conversion kernels -----------------------------------------
// fp32 -> fp16 (single)
__global__ __launch_bounds__(256) void cvt_kernel(
    const float* __restrict__ A, __half* __restrict__ H, int n4)
{
    int i = blockIdx.x * 256 + threadIdx.x;
    if (i >= n4) return;
    float4 v = ((const float4*)A)[i];
    ((__half2*)H)[i * 2 + 0] = __halves2half2(__float2half_rn(v.x), __float2half_rn(v.y));
    ((__half2*)H)[i * 2 + 1] = __halves2half2(__float2half_rn(v.z), __float2half_rn(v.w));
}

// transpose + round: W [K x N] fp32 -> H [N x K] fp16
__global__ __launch_bounds__(256) void tsplit_kernel(
    const float* __restrict__ W, __half* __restrict__ H, int K, int N)
{
    __shared__ float t[32][33];
    const int tx = threadIdx.x, ty = threadIdx.y;
    const int bk = blockIdx.y * 32, bn = blockIdx.x * 32;
    #pragma unroll
    for (int j = 0; j < 4; ++j)
        t[ty + j * 8][tx] = W[(size_t)(bk + ty + j * 8) * N + bn + tx];
    __syncthreads();
    #pragma unroll
    for (int j = 0; j < 4; ++j) {
        int r = ty + j * 8;
        H[(size_t)(bn + r) * K + bk + tx] = __float2half_rn(t[tx][r]);
    }
}

// ---------------- single-fp16 tensor-core GEMM -------------------------------
// C = act(A @ B^T + bias); A [M,K] fp16, B [N,K] fp16, fp32 accum.
// Tile 128x128, BK=32, 8 warps, 1 MMA per fragment pair.
// Output: fp32 (Cf) or fp16 (Ch; plus hi/lo into Ch/Cl for cols < loN).
#define G_PART  8192
#define G_STAGE (2 * G_PART)
#define G_SMEM  (2 * G_STAGE)

__global__ __launch_bounds__(256) void gemm_tc_kernel(
    const __half* __restrict__ Ah, const __half* __restrict__ Bh,
    const float* __restrict__ bias,
    float* __restrict__ Cf, __half* __restrict__ Ch, __half* __restrict__ Cl,
    int M, int N, int K, int act, int loN)
{
    extern __shared__ char smem[];
    const uint32_t sb = smem_u32(smem);
    const int tid = threadIdx.x;
    const int wid = tid >> 5, lane = tid & 31;
    const int warp_m = wid >> 2, warp_n = wid & 3;
    const int bm = blockIdx.y * 128, bn = blockIdx.x * 128;

    float acc[4][4][4];
    #pragma unroll
    for (int i = 0; i < 4; ++i)
        #pragma unroll
        for (int j = 0; j < 4; ++j)
            #pragma unroll
            for (int r = 0; r < 4; ++r) acc[i][j][r] = 0.f;

    const int swz = (lane & 7) >> 1;
    const int rA = warp_m * 64 + ((lane >> 3) & 1) * 8 + (lane & 7);
    const int kA = lane >> 4;
    const int rB = warp_n * 32 + (lane >> 4) * 8 + (lane & 7);
    const int kB = (lane >> 3) & 1;

    const int nst = K >> 5;

    auto load_stage = [&](int j) {
        const uint32_t st = sb + (uint32_t)(j & 1) * G_STAGE;
        const int kc = j * 32;
        #pragma unroll
        for (int t = 0; t < 2; ++t) {
            int idx = tid + t * 256;
            int row = idx >> 2, ch = idx & 3;
            uint32_t so = (uint32_t)row * 64 + (uint32_t)((ch ^ ((row >> 1) & 3)) << 4);
            size_t ga = (size_t)(bm + row) * K + kc + ch * 8;
            size_t gb = (size_t)(bn + row) * K + kc + ch * 8;
            CP_ASYNC16(st + 0 * G_PART + so, Ah + ga);
            CP_ASYNC16(st + 1 * G_PART + so, Bh + gb);
        }
        CP_COMMIT();
    };

    load_stage(0);

    for (int j = 0; j < nst; ++j) {
        if (j + 1 < nst) { load_stage(j + 1); CP_WAIT(1); }
        else             { CP_WAIT(0); }
        __syncthreads();

        const uint32_t st = sb + (uint32_t)(j & 1) * G_STAGE;
        #pragma unroll
        for (int ks = 0; ks < 2; ++ks) {
            uint32_t ah[4][4], bh[2][4];
            #pragma unroll
            for (int mt = 0; mt < 4; ++mt) {
                uint32_t ao = (uint32_t)(rA + mt * 16) * 64
                            + (uint32_t)(((ks * 2 + kA) ^ swz) << 4);
                LDSM_X4(ah[mt], st + 0 * G_PART + ao);
            }
            #pragma unroll
            for (int np = 0; np < 2; ++np) {
                uint32_t bo = (uint32_t)(rB + np * 16) * 64
                            + (uint32_t)(((ks * 2 + kB) ^ swz) << 4);
                LDSM_X4(bh[np], st + 1 * G_PART + bo);
            }
            #pragma unroll
            for (int mt = 0; mt < 4; ++mt)
                #pragma unroll
                for (int nt = 0; nt < 4; ++nt) {
                    const uint32_t* bhp = &bh[nt >> 1][(nt & 1) * 2];
                    MMAF16(acc[mt][nt], ah[mt], bhp[0], bhp[1]);
                }
        }
        __syncthreads();
    }

    // epilogue
    const bool wlo = (Cl != nullptr) && (bn < loN);
    #pragma unroll
    for (int mt = 0; mt < 4; ++mt)
        #pragma unroll
        for (int nt = 0; nt < 4; ++nt) {
            int row0 = bm + warp_m * 64 + mt * 16 + (lane >> 2);
            int col  = bn + warp_n * 32 + nt * 8 + (lane & 3) * 2;
            float b0 = bias[col], b1 = bias[col + 1];
            float v[4];
            v[0] = acc[mt][nt][0] + b0;
            v[1] = acc[mt][nt][1] + b1;
            v[2] = acc[mt][nt][2] + b0;
            v[3] = acc[mt][nt][3] + b1;
            if (act) {
                #pragma unroll
                for (int r = 0; r < 4; ++r)
                    v[r] = 0.5f * v[r] * (1.f + erff(v[r] * 0.70710678118654752f));
            }
            if (Cf) {
                *(float2*)&Cf[(size_t)row0 * N + col]       = make_float2(v[0], v[1]);
                *(float2*)&Cf[(size_t)(row0 + 8) * N + col] = make_float2(v[2], v[3]);
            } else if (wlo) {
                __half h0, h1, l0, l1;
                split_h(v[0], h0, l0); split_h(v[1], h1, l1);
                *(__half2*)&Ch[(size_t)row0 * N + col] = __halves2half2(h0, h1);
                *(__half2*)&Cl[(size_t)row0 * HID + col] = __halves2half2(l0, l1);
                split_h(v[2], h0, l0); split_h(v[3], h1, l1);
                *(__half2*)&Ch[(size_t)(row0 + 8) * N + col] = __halves2half2(h0, h1);
                *(__half2*)&Cl[(size_t)(row0 + 8) * HID + col] = __halves2half2(l0, l1);
            } else {
                *(__half2*)&Ch[(size_t)row0 * N + col] =
                    __halves2half2(__float2half_rn(v[0]), __float2half_rn(v[1]));
                *(__half2*)&Ch[(size_t)(row0 + 8) * N + col] =
                    __halves2half2(__float2half_rn(v[2]), __float2half_rn(v[3]));
            }
        }
}

// ---------------- tensor-core attention with head-axis softmax ----------------
// QKV: Ph [4096][3072] fp16, Pl [4096][1024] fp16 (Q lo only).
// Per block (a, n): 16 warps, warp = head. Q split, K/V single, W split.
#define SCW(hh, b, p) ((hh) * 290 + (b) * 18 + (p))
#define AT_STG 65536                 // K (32KB) + V (32KB) per stage
#define ATTN_SMEM (2 * AT_STG + 290 * 16 * 4)

__global__ __launch_bounds__(512, 1) void attn_kernel(
    const __half* __restrict__ Ph, const __half* __restrict__ Pl,
    __half* __restrict__ Oh)
{
    extern __shared__ char smem[];
    const uint32_t sb = smem_u32(smem);
    float* sc = (float*)(smem + 2 * AT_STG);

    const int tid = threadIdx.x, lane = tid & 31, h = tid >> 5;
    const int a = blockIdx.x, n = blockIdx.y;
    const int lr = lane >> 2, lc = lane & 3;

    // ---- stage Q (hi into [0,32K), lo into [32K,64K)), extract fragments ----
    {
        #pragma unroll
        for (int t = 0; t < 4; ++t) {
            int f = tid + t * 512;
            int hh = f >> 7, bp = (f >> 3) & 15, c = f & 7;
            uint32_t dst = (uint32_t)hh * 2048 + bp * 128 + ((c ^ (bp & 7)) << 4);
            size_t srch = (size_t)(n * 1024 + hh * 64 + a) * 3072 + bp * 64 + c * 8;
            size_t srcl = (size_t)(n * 1024 + hh * 64 + a) * 1024 + bp * 64 + c * 8;
            CP_ASYNC16(sb + dst,         Ph + srch);
            CP_ASYNC16(sb + 32768 + dst, Pl + srcl);
        }
        CP_COMMIT(); CP_WAIT(0); __syncthreads();
    }
    uint32_t qh[4][4], ql[4][4];
    {
        int b = lane & 15, cs = lane >> 4;
        #pragma unroll
        for (int ks = 0; ks < 4; ++ks) {
            uint32_t ad = (uint32_t)h * 2048 + b * 128
                        + (((ks * 2 + cs) ^ (b & 7)) << 4);
            LDSM_X4(qh[ks], sb + ad);
            LDSM_X4(ql[ks], sb + 32768 + ad);
        }
    }
    __syncthreads();   // everyone done reading Q before KV overwrites stage 0

    auto stageKV = [&](int ap, int s) {
        uint32_t base = sb + (uint32_t)s * AT_STG;
        #pragma unroll
        for (int t = 0; t < 4; ++t) {
            int f = tid + t * 512;
            int hh = f >> 7, bp = (f >> 3) & 15, c = f & 7;
            uint32_t dst = (uint32_t)hh * 2048 + bp * 128 + ((c ^ (bp & 7)) << 4);
            size_t row = (size_t)(n * 1024 + hh * 64 + ap) * 3072;
            CP_ASYNC16(base + dst,         Ph + row + 1024 + bp * 64 + c * 8);
            CP_ASYNC16(base + 32768 + dst, Ph + row + 2048 + bp * 64 + c * 8);
        }
        CP_COMMIT();
    };

    float o[8][4];
    #pragma unroll
    for (int nt = 0; nt < 8; ++nt)
        #pragma unroll
        for (int r = 0; r < 4; ++r) o[nt][r] = 0.f;

    stageKV(0, 0);
    for (int ap = 0; ap < 64; ++ap) {
        const int s = ap & 1;
        if (ap + 1 < 64) { stageKV(ap + 1, s ^ 1); CP_WAIT(1); }
        else             { CP_WAIT(0); }
        __syncthreads();

        const uint32_t kb = sb + (uint32_t)s * AT_STG;
        const uint32_t vb = kb + 32768;

        // ---- scores: S = (Qh+Ql) K^T ----
        float sv[2][4];
        #pragma unroll
        for (int nt = 0; nt < 2; ++nt)
            #pragma unroll
            for (int r = 0; r < 4; ++r) sv[nt][r] = 0.f;
        {
            int bpr = lane & 7, khalf = (lane >> 3) & 1;
            #pragma unroll
            for (int ks = 0; ks < 4; ++ks)
                #pragma unroll
                for (int nt = 0; nt < 2; ++nt) {
                    int row = nt * 8 + bpr;
                    uint32_t ad = (uint32_t)h * 2048 + row * 128
                                + (((ks * 2 + khalf) ^ (row & 7)) << 4);
                    uint32_t k2[2];
                    LDSM_X2(k2, kb + ad);
                    MMAF16(sv[nt], qh[ks], k2[0], k2[1]);
                    MMAF16(sv[nt], ql[ks], k2[0], k2[1]);
                }
        }
        #pragma unroll
        for (int nt = 0; nt < 2; ++nt) {
            int c0 = nt * 8 + 2 * lc;
            sc[SCW(h, lr,     c0)]     = sv[nt][0] * 0.03125f;
            sc[SCW(h, lr,     c0 + 1)] = sv[nt][1] * 0.03125f;
            sc[SCW(h, lr + 8, c0)]     = sv[nt][2] * 0.03125f;
            sc[SCW(h, lr + 8, c0 + 1)] = sv[nt][3] * 0.03125f;
        }
        __syncthreads();

        // ---- head-softmax: thread p owns (b = p>>4, b' = p&15) ----
        if (tid < 256) {
            const int pb = tid >> 4, pbp = tid & 15;
            float m = -1e30f;
            #pragma unroll
            for (int hh = 0; hh < 16; ++hh) m = fmaxf(m, sc[SCW(hh, pb, pbp)]);
            float ssum = 0.f;
            #pragma unroll
            for (int hh = 0; hh < 16; ++hh) {
                float e = __expf(sc[SCW(hh, pb, pbp)] - m);
                ssum += e;
                sc[SCW(hh, pb, pbp)] = e;
            }
            float inv = 1.f / ssum;
            #pragma unroll
            for (int hh = 0; hh < 16; ++hh) sc[SCW(hh, pb, pbp)] *= inv;
        }
        __syncthreads();

        // ---- W fragments (fp16 hi/lo of the exact fp32 weights) ----
        uint32_t awh[4], awl[4];
        {
            float wv[8];
            wv[0] = sc[SCW(h, lr,     2 * lc)];
            wv[1] = sc[SCW(h, lr,     2 * lc + 1)];
            wv[2] = sc[SCW(h, lr + 8, 2 * lc)];
            wv[3] = sc[SCW(h, lr + 8, 2 * lc + 1)];
            wv[4] = sc[SCW(h, lr,     2 * lc + 8)];
            wv[5] = sc[SCW(h, lr,     2 * lc + 9)];
            wv[6] = sc[SCW(h, lr + 8, 2 * lc + 8)];
            wv[7] = sc[SCW(h, lr + 8, 2 * lc + 9)];
            #pragma unroll
            for (int i = 0; i < 4; ++i) {
                __half h0, h1, l0, l1;
                split_h(wv[2 * i],     h0, l0);
                split_h(wv[2 * i + 1], h1, l1);
                awh[i] = pack_h2(h0, h1);
                awl[i] = pack_h2(l0, l1);
            }
        }

        // ---- AV: O += (Wh+Wl) V (V via ldmatrix.trans) ----
        {
            int bp = lane & 15;
            #pragma unroll
            for (int nt = 0; nt < 8; ++nt) {
                uint32_t ad = (uint32_t)h * 2048 + bp * 128
                            + ((nt ^ (bp & 7)) << 4);
                uint32_t v2[2];
                LDSM_X2T(v2, vb + ad);
                MMAF16(o[nt], awh, v2[0], v2[1]);
                MMAF16(o[nt], awl, v2[0], v2[1]);
            }
        }
        __syncthreads();   // all reads of buffer s / sc done before next overwrite
    }

    // ---- write O (one 1024-col row per head) as fp16 ----
    const size_t orow = (size_t)(n * 1024 + h * 64 + a) * 1024;
    #pragma unroll
    for (int nt = 0; nt < 8; ++nt) {
        int c0 = nt * 8 + 2 * lc;
        *(__half2*)(Oh + orow + lr * 64 + c0) =
            __halves2half2(__float2half_rn(o[nt][0]), __float2half_rn(o[nt][1]));
        *(__half2*)(Oh + orow + (lr + 8) * 64 + c0) =
            __halves2half2(__float2half_rn(o[nt][2]), __float2half_rn(o[nt][3]));
    }
}

// ---------------- fused residual + LayerNorm (+ optional fp16 emit) ----------
__global__ __launch_bounds__(256) void ln_kernel(
    const float* __restrict__ A, const float* __restrict__ R,
    const float* __restrict__ g, const float* __restrict__ bta,
    float* __restrict__ out, __half* __restrict__ Xh)
{
    __shared__ float red[16];
    const int row = blockIdx.x;
    const int tid = threadIdx.x;

    float4 v = ((const float4*)(A + (size_t)row * 1024))[tid];
    float4 r = ((const float4*)(R + (size_t)row * 1024))[tid];
    v.x += r.x; v.y += r.y; v.z += r.z; v.w += r.w;

    float s  = v.x + v.y + v.z + v.w;
    float sq = v.x * v.x + v.y * v.y + v.z * v.z + v.w * v.w;
    #pragma unroll
    for (int o = 16; o > 0; o >>= 1) {
        s  += __shfl_xor_sync(0xffffffffu, s,  o);
        sq += __shfl_xor_sync(0xffffffffu, sq, o);
    }
    if ((tid & 31) == 0) { red[tid >> 5] = s; red[8 + (tid >> 5)] = sq; }
    __syncthreads();
    float S = 0.f, SQ = 0.f;
    #pragma unroll
    for (int w = 0; w < 8; ++w) { S += red[w]; SQ += red[8 + w]; }

    const float mean = S * (1.f / 1024.f);
    const float var  = SQ * (1.f / 1024.f) - mean * mean;
    const float rstd = rsqrtf(var + 1e-5f);

    float4 gv = ((const float4*)g)[tid];
    float4 bv = ((const float4*)bta)[tid];
    float4 o;
    o.x = (v.x - mean) * rstd * gv.x + bv.x;
    o.y = (v.y - mean) * rstd * gv.y + bv.y;
    o.z = (v.z - mean) * rstd * gv.z + bv.z;
    o.w = (v.w - mean) * rstd * gv.w + bv.w;
    ((float4*)(out + (size_t)row * 1024))[tid] = o;

    if (Xh) {
        size_t oo = (size_t)row * 1024 + tid * 4;
        *(__half2*)(Xh + oo)     = __halves2half2(__float2half_rn(o.x), __float2half_rn(o.y));
        *(__half2*)(Xh + oo + 2) = __halves2half2(__float2half_rn(o.z), __float2half_rn(o.w));
    }
}

// ---------------- launch ------------------------------------------------------
extern "C" void kernel_launch(void* const* d_in, const int* in_sizes, int n_in,
                              void* d_out, int out_size)
{
    const float* x  = (const float*)d_in[0];
    const float* Wq = (const float*)d_in[1];
    const float* bq = (const float*)d_in[2];
    const float* Wk = (const float*)d_in[3];
    const float* bk = (const float*)d_in[4];
    const float* Wv = (const float*)d_in[5];
    const float* bv = (const float*)d_in[6];
    const float* Wo = (const float*)d_in[7];
    const float* bo = (const float*)d_in[8];
    const float* g1 = (const float*)d_in[9];
    const float* b1 = (const float*)d_in[10];
    const float* W1 = (const float*)d_in[11];
    const float* c1 = (const float*)d_in[12];
    const float* W2 = (const float*)d_in[13];
    const float* c2 = (const float*)d_in[14];
    const float* g2 = (const float*)d_in[15];
    const float* b2 = (const float*)d_in[16];
    float* out = (float*)d_out;

    float *pX1, *pF, *pbqkv;
    __half *pAh, *pHh, *pHl, *pBh;
    cudaGetSymbolAddress((void**)&pX1,  g_X1);
    cudaGetSymbolAddress((void**)&pF,   g_F);
    cudaGetSymbolAddress((void**)&pbqkv,g_bqkv);
    cudaGetSymbolAddress((void**)&pAh,  g_Ah);
    cudaGetSymbolAddress((void**)&pHh,  g_Hh);
    cudaGetSymbolAddress((void**)&pHl,  g_Hl);
    cudaGetSymbolAddress((void**)&pBh,  g_Bh);

    cudaFuncSetAttribute(attn_kernel, cudaFuncAttributeMaxDynamicSharedMemorySize, ATTN_SMEM);
    cudaFuncSetAttribute(gemm_tc_kernel, cudaFuncAttributeMaxDynamicSharedMemorySize, G_SMEM);

    dim3 blk(256);
    dim3 t32(32, 8);
    const int n4_1 = NTOK * HID / 4;
    dim3 gs1((n4_1 + 255) / 256);
    dim3 tg11(HID / 32, HID / 32);
    dim3 tg14(4 * HID / 32, HID / 32);
    dim3 tg41(HID / 32, 4 * HID / 32);
    dim3 ggqkv(3 * HID / 128, NTOK / 128);
    dim3 gg1(HID / 128, NTOK / 128);
    dim3 gg4(4 * HID / 128, NTOK / 128);

    // ---- QKV: round x, round W_{q,k,v}^T, one N=3072 GEMM ----
    cvt_kernel<<<gs1, blk>>>(x, pAh, n4_1);
    tsplit_kernel<<<tg11, t32>>>(Wq, pBh,               HID, HID);
    tsplit_kernel<<<tg11, t32>>>(Wk, pBh + 1024 * 1024, HID, HID);
    tsplit_kernel<<<tg11, t32>>>(Wv, pBh + 2048 * 1024, HID, HID);
    cudaMemcpyAsync(pbqkv,        bq, HID * 4, cudaMemcpyDeviceToDevice, 0);
    cudaMemcpyAsync(pbqkv + 1024, bk, HID * 4, cudaMemcpyDeviceToDevice, 0);
    cudaMemcpyAsync(pbqkv + 2048, bv, HID * 4, cudaMemcpyDeviceToDevice, 0);
    gemm_tc_kernel<<<ggqkv, blk, G_SMEM>>>(pAh, pBh, pbqkv,
                                           nullptr, pHh, pHl,
                                           NTOK, 3 * HID, HID, 0, HID);

    // ---- tensor-core attention; emits O fp16 ----
    attn_kernel<<<dim3(64, 4), 512, ATTN_SMEM>>>(pHh, pHl, pAh);

    // ---- output projection, residual + LN1 (emits X1 fp32 + fp16) ----
    tsplit_kernel<<<tg11, t32>>>(Wo, pBh, HID, HID);
    gemm_tc_kernel<<<gg1, blk, G_SMEM>>>(pAh, pBh, bo,
                                         pF, nullptr, nullptr,
                                         NTOK, HID, HID, 0, 0);
    ln_kernel<<<NTOK, blk>>>(pF, x, g1, b1, pX1, pAh);

    // ---- FFN ----
    tsplit_kernel<<<tg14, t32>>>(W1, pBh, HID, 4 * HID);
    gemm_tc_kernel<<<gg4, blk, G_SMEM>>>(pAh, pBh, c1,
                                         nullptr, pHh, nullptr,
                                         NTOK, 4 * HID, HID, 1, 0);
    tsplit_kernel<<<tg41, t32>>>(W2, pBh, 4 * HID, HID);
    gemm_tc_kernel<<<gg1, blk, G_SMEM>>>(pHh, pBh, c2,
                                         pF, nullptr, nullptr,
                                         NTOK, HID, 4 * HID, 0, 0);

    // ---- residual + LN2 -> output ----
    ln_kernel<<<NTOK, blk>>>(pF, pX1, g2, b2, out, nullptr);
}

// round 9
// speedup vs baseline: 3.1660x; 1.0511x over previous
#include <cuda_runtime.h>
#include <cuda_fp16.h>
#include <stdint.h>
#include <math.h>

// ---------------- scratch buffers (static device memory, no allocs) ----------
#define NTOK 4096              // 4 * 1024 rows
#define HID  1024
__device__ float g_X1 [NTOK * HID];
__device__ float g_F  [NTOK * HID];
__device__ float g_bqkv[3 * HID];
__device__ __half g_Ah[NTOK * HID];       // activations fp16 (x / O / X1)
__device__ __half g_Hh[NTOK * 4 * HID];   // QKV, later FF hidden
__device__ __half g_Bh[4 * HID * HID];    // transposed weights fp16

// ---------------- PTX helpers (arch-neutral only) -----------------------------
__device__ __forceinline__ uint32_t smem_u32(const void* p) {
    uint32_t a;
    asm("{ .reg .u64 t; cvta.to.shared.u64 t, %1; cvt.u32.u64 %0, t; }"
        : "=r"(a) : "l"(p));
    return a;
}
#define CP_ASYNC16(s, g) \
    asm volatile("cp.async.cg.shared.global [%0], [%1], 16;" :: "r"(s), "l"(g))
#define CP_COMMIT() asm volatile("cp.async.commit_group;" ::: "memory")
#define CP_WAIT(n)  asm volatile("cp.async.wait_group %0;" :: "n"(n) : "memory")
#define LDSM_X4(r, addr) \
    asm volatile("ldmatrix.sync.aligned.m8n8.x4.shared.b16 {%0,%1,%2,%3}, [%4];" \
        : "=r"((r)[0]), "=r"((r)[1]), "=r"((r)[2]), "=r"((r)[3]) : "r"(addr))
#define LDSM_X2(r, addr) \
    asm volatile("ldmatrix.sync.aligned.m8n8.x2.shared.b16 {%0,%1}, [%2];" \
        : "=r"((r)[0]), "=r"((r)[1]) : "r"(addr))
#define LDSM_X2T(r, addr) \
    asm volatile("ldmatrix.sync.aligned.m8n8.x2.trans.shared.b16 {%0,%1}, [%2];" \
        : "=r"((r)[0]), "=r"((r)[1]) : "r"(addr))
#define MMAF16(c, a, b0, b1) \
    asm volatile("mma.sync.aligned.m16n8k16.row.col.f32.f16.f16.f32 " \
        "{%0,%1,%2,%3}, {%4,%5,%6,%7}, {%8,%9}, {%0,%1,%2,%3};" \
        : "+f"((c)[0]), "+f"((c)[1]), "+f"((c)[2]), "+f"((c)[3]) \
        : "r"((a)[0]), "r"((a)[1]), "r"((a)[2]), "r"((a)[3]), "r"(b0), "r"(b1))

__device__ __forceinline__ uint32_t pack_h2f(float x, float y) {
    __half2 p = __halves2half2(__float2half_rn(x), __float2half_rn(y));
    return *reinterpret_cast<uint32_t*>(&p);
}

// ---------------- conversion kernels -----------------------------------------
// fp32 -> fp16
__global__ __launch_bounds__(256) void cvt_kernel(
    const float* __restrict__ A, __half* __restrict__ H, int n4)
{
    int i = blockIdx.x * 256 + threadIdx.x;
    if (i >= n4) return;
    float4 v = ((const float4*)A)[i];
    ((__half2*)H)[i * 2 + 0] = __halves2half2(__float2half_rn(v.x), __float2half_rn(v.y));
    ((__half2*)H)[i * 2 + 1] = __halves2half2(__float2half_rn(v.z), __float2half_rn(v.w));
}

// transpose + round: W [K x N] fp32 -> H [N x K] fp16
__global__ __launch_bounds__(256) void tsplit_kernel(
    const float* __restrict__ W, __half* __restrict__ H, int K, int N)
{
    __shared__ float t[32][33];
    const int tx = threadIdx.x, ty = threadIdx.y;
    const int bk = blockIdx.y * 32, bn = blockIdx.x * 32;
    #pragma unroll
    for (int j = 0; j < 4; ++j)
        t[ty + j * 8][tx] = W[(size_t)(bk + ty + j * 8) * N + bn + tx];
    __syncthreads();
    #pragma unroll
    for (int j = 0; j < 4; ++j) {
        int r = ty + j * 8;
        H[(size_t)(bn + r) * K + bk + tx] = __float2half_rn(t[tx][r]);
    }
}

// batched variant: three same-shape weights (QKV) in one launch via blockIdx.z
__global__ __launch_bounds__(256) void tsplit3_kernel(
    const float* __restrict__ W0, const float* __restrict__ W1,
    const float* __restrict__ W2, __half* __restrict__ H, int K, int N)
{
    __shared__ float t[32][33];
    const float* W = (blockIdx.z == 0) ? W0 : (blockIdx.z == 1) ? W1 : W2;
    __half* Hd = H + (size_t)blockIdx.z * N * K;
    const int tx = threadIdx.x, ty = threadIdx.y;
    const int bk = blockIdx.y * 32, bn = blockIdx.x * 32;
    #pragma unroll
    for (int j = 0; j < 4; ++j)
        t[ty + j * 8][tx] = W[(size_t)(bk + ty + j * 8) * N + bn + tx];
    __syncthreads();
    #pragma unroll
    for (int j = 0; j < 4; ++j) {
        int r = ty + j * 8;
        Hd[(size_t)(bn + r) * K + bk + tx] = __float2half_rn(t[tx][r]);
    }
}

// ---------------- single-fp16 tensor-core GEMM -------------------------------
// C = act(A @ B^T + bias); A [M,K] fp16, B [N,K] fp16, fp32 accum.
// Tile 128x128, BK=32, 8 warps. Output fp32 (Cf) or fp16 (Ch).
#define G_PART  8192
#define G_STAGE (2 * G_PART)
#define G_SMEM  (2 * G_STAGE)

__global__ __launch_bounds__(256) void gemm_tc_kernel(
    const __half* __restrict__ Ah, const __half* __restrict__ Bh,
    const float* __restrict__ bias,
    float* __restrict__ Cf, __half* __restrict__ Ch,
    int M, int N, int K, int act)
{
    extern __shared__ char smem[];
    const uint32_t sb = smem_u32(smem);
    const int tid = threadIdx.x;
    const int wid = tid >> 5, lane = tid & 31;
    const int warp_m = wid >> 2, warp_n = wid & 3;
    const int bm = blockIdx.y * 128, bn = blockIdx.x * 128;

    float acc[4][4][4];
    #pragma unroll
    for (int i = 0; i < 4; ++i)
        #pragma unroll
        for (int j = 0; j < 4; ++j)
            #pragma unroll
            for (int r = 0; r < 4; ++r) acc[i][j][r] = 0.f;

    const int swz = (lane & 7) >> 1;
    const int rA = warp_m * 64 + ((lane >> 3) & 1) * 8 + (lane & 7);
    const int kA = lane >> 4;
    const int rB = warp_n * 32 + (lane >> 4) * 8 + (lane & 7);
    const int kB = (lane >> 3) & 1;

    const int nst = K >> 5;

    auto load_stage = [&](int j) {
        const uint32_t st = sb + (uint32_t)(j & 1) * G_STAGE;
        const int kc = j * 32;
        #pragma unroll
        for (int t = 0; t < 2; ++t) {
            int idx = tid + t * 256;
            int row = idx >> 2, ch = idx & 3;
            uint32_t so = (uint32_t)row * 64 + (uint32_t)((ch ^ ((row >> 1) & 3)) << 4);
            size_t ga = (size_t)(bm + row) * K + kc + ch * 8;
            size_t gb = (size_t)(bn + row) * K + kc + ch * 8;
            CP_ASYNC16(st + 0 * G_PART + so, Ah + ga);
            CP_ASYNC16(st + 1 * G_PART + so, Bh + gb);
        }
        CP_COMMIT();
    };

    load_stage(0);

    for (int j = 0; j < nst; ++j) {
        if (j + 1 < nst) { load_stage(j + 1); CP_WAIT(1); }
        else             { CP_WAIT(0); }
        __syncthreads();

        const uint32_t st = sb + (uint32_t)(j & 1) * G_STAGE;
        #pragma unroll
        for (int ks = 0; ks < 2; ++ks) {
            uint32_t ah[4][4], bh[2][4];
            #pragma unroll
            for (int mt = 0; mt < 4; ++mt) {
                uint32_t ao = (uint32_t)(rA + mt * 16) * 64
                            + (uint32_t)(((ks * 2 + kA) ^ swz) << 4);
                LDSM_X4(ah[mt], st + 0 * G_PART + ao);
            }
            #pragma unroll
            for (int np = 0; np < 2; ++np) {
                uint32_t bo = (uint32_t)(rB + np * 16) * 64
                            + (uint32_t)(((ks * 2 + kB) ^ swz) << 4);
                LDSM_X4(bh[np], st + 1 * G_PART + bo);
            }
            #pragma unroll
            for (int mt = 0; mt < 4; ++mt)
                #pragma unroll
                for (int nt = 0; nt < 4; ++nt) {
                    const uint32_t* bhp = &bh[nt >> 1][(nt & 1) * 2];
                    MMAF16(acc[mt][nt], ah[mt], bhp[0], bhp[1]);
                }
        }
        __syncthreads();
    }

    // epilogue
    #pragma unroll
    for (int mt = 0; mt < 4; ++mt)
        #pragma unroll
        for (int nt = 0; nt < 4; ++nt) {
            int row0 = bm + warp_m * 64 + mt * 16 + (lane >> 2);
            int col  = bn + warp_n * 32 + nt * 8 + (lane & 3) * 2;
            float b0 = bias[col], b1 = bias[col + 1];
            float v[4];
            v[0] = acc[mt][nt][0] + b0;
            v[1] = acc[mt][nt][1] + b1;
            v[2] = acc[mt][nt][2] + b0;
            v[3] = acc[mt][nt][3] + b1;
            if (act) {
                #pragma unroll
                for (int r = 0; r < 4; ++r)
                    v[r] = 0.5f * v[r] * (1.f + erff(v[r] * 0.70710678118654752f));
            }
            if (Cf) {
                *(float2*)&Cf[(size_t)row0 * N + col]       = make_float2(v[0], v[1]);
                *(float2*)&Cf[(size_t)(row0 + 8) * N + col] = make_float2(v[2], v[3]);
            } else {
                *(__half2*)&Ch[(size_t)row0 * N + col] =
                    *reinterpret_cast<__half2*>(&(uint32_t&)*(uint32_t[]){pack_h2f(v[0], v[1])});
                *(__half2*)&Ch[(size_t)(row0 + 8) * N + col] =
                    *reinterpret_cast<__half2*>(&(uint32_t&)*(uint32_t[]){pack_h2f(v[2], v[3])});
            }
        }
}

// ---------------- tensor-core attention (single fp16, head-axis softmax) ------
// QKV packed fp16 [4096][3072]. Per block (a, n): 16 warps, warp = head.
#define SCW(hh, b, p) ((hh) * 290 + (b) * 18 + (p))
#define AT_STG 65536                 // K (32KB) + V (32KB) per stage
#define ATTN_SMEM (2 * AT_STG + 290 * 16 * 4)

__global__ __launch_bounds__(512, 1) void attn_kernel(
    const __half* __restrict__ Ph, __half* __restrict__ Oh)
{
    extern __shared__ char smem[];
    const uint32_t sb = smem_u32(smem);
    float* sc = (float*)(smem + 2 * AT_STG);

    const int tid = threadIdx.x, lane = tid & 31, h = tid >> 5;
    const int a = blockIdx.x, n = blockIdx.y;
    const int lr = lane >> 2, lc = lane & 3;

    // ---- stage Q into stage-0 area, extract fragments ----
    {
        #pragma unroll
        for (int t = 0; t < 4; ++t) {
            int f = tid + t * 512;
            if (f < 2048) {
                int hh = f >> 7, bp = (f >> 3) & 15, c = f & 7;
                uint32_t dst = (uint32_t)hh * 2048 + bp * 128 + ((c ^ (bp & 7)) << 4);
                size_t src = (size_t)(n * 1024 + hh * 64 + a) * 3072 + bp * 64 + c * 8;
                CP_ASYNC16(sb + dst, Ph + src);
            }
        }
        CP_COMMIT(); CP_WAIT(0); __syncthreads();
    }
    uint32_t qh[4][4];
    {
        int b = lane & 15, cs = lane >> 4;
        #pragma unroll
        for (int ks = 0; ks < 4; ++ks) {
            uint32_t ad = (uint32_t)h * 2048 + b * 128
                        + (((ks * 2 + cs) ^ (b & 7)) << 4);
            LDSM_X4(qh[ks], sb + ad);
        }
    }
    __syncthreads();   // everyone done reading Q before KV overwrites stage 0

    auto stageKV = [&](int ap, int s) {
        uint32_t base = sb + (uint32_t)s * AT_STG;
        #pragma unroll
        for (int t = 0; t < 4; ++t) {
            int f = tid + t * 512;
            int hh = f >> 7, bp = (f >> 3) & 15, c = f & 7;
            uint32_t dst = (uint32_t)hh * 2048 + bp * 128 + ((c ^ (bp & 7)) << 4);
            size_t row = (size_t)(n * 1024 + hh * 64 + ap) * 3072;
            CP_ASYNC16(base + dst,         Ph + row + 1024 + bp * 64 + c * 8);
            CP_ASYNC16(base + 32768 + dst, Ph + row + 2048 + bp * 64 + c * 8);
        }
        CP_COMMIT();
    };

    float o[8][4];
    #pragma unroll
    for (int nt = 0; nt < 8; ++nt)
        #pragma unroll
        for (int r = 0; r < 4; ++r) o[nt][r] = 0.f;

    stageKV(0, 0);
    for (int ap = 0; ap < 64; ++ap) {
        const int s = ap & 1;
        if (ap + 1 < 64) { stageKV(ap + 1, s ^ 1); CP_WAIT(1); }
        else             { CP_WAIT(0); }
        __syncthreads();

        const uint32_t kb = sb + (uint32_t)s * AT_STG;
        const uint32_t vb = kb + 32768;

        // ---- scores: S = Q K^T ----
        float sv[2][4];
        #pragma unroll
        for (int nt = 0; nt < 2; ++nt)
            #pragma unroll
            for (int r = 0; r < 4; ++r) sv[nt][r] = 0.f;
        {
            int bpr = lane & 7, khalf = (lane >> 3) & 1;
            #pragma unroll
            for (int ks = 0; ks < 4; ++ks)
                #pragma unroll
                for (int nt = 0; nt < 2; ++nt) {
                    int row = nt * 8 + bpr;
                    uint32_t ad = (uint32_t)h * 2048 + row * 128
                                + (((ks * 2 + khalf) ^ (row & 7)) << 4);
                    uint32_t k2[2];
                    LDSM_X2(k2, kb + ad);
                    MMAF16(sv[nt], qh[ks], k2[0], k2[1]);
                }
        }
        #pragma unroll
        for (int nt = 0; nt < 2; ++nt) {
            int c0 = nt * 8 + 2 * lc;
            sc[SCW(h, lr,     c0)]     = sv[nt][0] * 0.03125f;
            sc[SCW(h, lr,     c0 + 1)] = sv[nt][1] * 0.03125f;
            sc[SCW(h, lr + 8, c0)]     = sv[nt][2] * 0.03125f;
            sc[SCW(h, lr + 8, c0 + 1)] = sv[nt][3] * 0.03125f;
        }
        __syncthreads();

        // ---- head-softmax: thread p owns (b = p>>4, b' = p&15) ----
        if (tid < 256) {
            const int pb = tid >> 4, pbp = tid & 15;
            float m = -1e30f;
            #pragma unroll
            for (int hh = 0; hh < 16; ++hh) m = fmaxf(m, sc[SCW(hh, pb, pbp)]);
            float ssum = 0.f;
            #pragma unroll
            for (int hh = 0; hh < 16; ++hh) {
                float e = __expf(sc[SCW(hh, pb, pbp)] - m);
                ssum += e;
                sc[SCW(hh, pb, pbp)] = e;
            }
            float inv = 1.f / ssum;
            #pragma unroll
            for (int hh = 0; hh < 16; ++hh) sc[SCW(hh, pb, pbp)] *= inv;
        }
        __syncthreads();

        // ---- W fragments (fp16) from softmaxed scores ----
        uint32_t awh[4];
        awh[0] = pack_h2f(sc[SCW(h, lr,     2 * lc)],     sc[SCW(h, lr,     2 * lc + 1)]);
        awh[1] = pack_h2f(sc[SCW(h, lr + 8, 2 * lc)],     sc[SCW(h, lr + 8, 2 * lc + 1)]);
        awh[2] = pack_h2f(sc[SCW(h, lr,     2 * lc + 8)], sc[SCW(h, lr,     2 * lc + 9)]);
        awh[3] = pack_h2f(sc[SCW(h, lr + 8, 2 * lc + 8)], sc[SCW(h, lr + 8, 2 * lc + 9)]);

        // ---- AV: O += W V (V via ldmatrix.trans) ----
        {
            int bp = lane & 15;
            #pragma unroll
            for (int nt = 0; nt < 8; ++nt) {
                uint32_t ad = (uint32_t)h * 2048 + bp * 128
                            + ((nt ^ (bp & 7)) << 4);
                uint32_t v2[2];
                LDSM_X2T(v2, vb + ad);
                MMAF16(o[nt], awh, v2[0], v2[1]);
            }
        }
        __syncthreads();   // all reads of buffer s / sc done before next overwrite
    }

    // ---- write O (one 1024-col row per head) as fp16 ----
    const size_t orow = (size_t)(n * 1024 + h * 64 + a) * 1024;
    #pragma unroll
    for (int nt = 0; nt < 8; ++nt) {
        int c0 = nt * 8 + 2 * lc;
        uint32_t p0 = pack_h2f(o[nt][0], o[nt][1]);
        uint32_t p1 = pack_h2f(o[nt][2], o[nt][3]);
        *(uint32_t*)(Oh + orow + lr * 64 + c0)       = p0;
        *(uint32_t*)(Oh + orow + (lr + 8) * 64 + c0) = p1;
    }
}

// ---------------- fused residual + LayerNorm (+ optional fp16 emit) ----------
__global__ __launch_bounds__(256) void ln_kernel(
    const float* __restrict__ A, const float* __restrict__ R,
    const float* __restrict__ g, const float* __restrict__ bta,
    float* __restrict__ out, __half* __restrict__ Xh)
{
    __shared__ float red[16];
    const int row = blockIdx.x;
    const int tid = threadIdx.x;

    float4 v = ((const float4*)(A + (size_t)row * 1024))[tid];
    float4 r = ((const float4*)(R + (size_t)row * 1024))[tid];
    v.x += r.x; v.y += r.y; v.z += r.z; v.w += r.w;

    float s  = v.x + v.y + v.z + v.w;
    float sq = v.x * v.x + v.y * v.y + v.z * v.z + v.w * v.w;
    #pragma unroll
    for (int o = 16; o > 0; o >>= 1) {
        s  += __shfl_xor_sync(0xffffffffu, s,  o);
        sq += __shfl_xor_sync(0xffffffffu, sq, o);
    }
    if ((tid & 31) == 0) { red[tid >> 5] = s; red[8 + (tid >> 5)] = sq; }
    __syncthreads();
    float S = 0.f, SQ = 0.f;
    #pragma unroll
    for (int w = 0; w < 8; ++w) { S += red[w]; SQ += red[8 + w]; }

    const float mean = S * (1.f / 1024.f);
    const float var  = SQ * (1.f / 1024.f) - mean * mean;
    const float rstd = rsqrtf(var + 1e-5f);

    float4 gv = ((const float4*)g)[tid];
    float4 bv = ((const float4*)bta)[tid];
    float4 o;
    o.x = (v.x - mean) * rstd * gv.x + bv.x;
    o.y = (v.y - mean) * rstd * gv.y + bv.y;
    o.z = (v.z - mean) * rstd * gv.z + bv.z;
    o.w = (v.w - mean) * rstd * gv.w + bv.w;
    ((float4*)(out + (size_t)row * 1024))[tid] = o;

    if (Xh) {
        size_t oo = (size_t)row * 1024 + tid * 4;
        *(__half2*)(Xh + oo)     = __halves2half2(__float2half_rn(o.x), __float2half_rn(o.y));
        *(__half2*)(Xh + oo + 2) = __halves2half2(__float2half_rn(o.z), __float2half_rn(o.w));
    }
}

// ---------------- launch ------------------------------------------------------
extern "C" void kernel_launch(void* const* d_in, const int* in_sizes, int n_in,
                              void* d_out, int out_size)
{
    const float* x  = (const float*)d_in[0];
    const float* Wq = (const float*)d_in[1];
    const float* bq = (const float*)d_in[2];
    const float* Wk = (const float*)d_in[3];
    const float* bk = (const float*)d_in[4];
    const float* Wv = (const float*)d_in[5];
    const float* bv = (const float*)d_in[6];
    const float* Wo = (const float*)d_in[7];
    const float* bo = (const float*)d_in[8];
    const float* g1 = (const float*)d_in[9];
    const float* b1 = (const float*)d_in[10];
    const float* W1 = (const float*)d_in[11];
    const float* c1 = (const float*)d_in[12];
    const float* W2 = (const float*)d_in[13];
    const float* c2 = (const float*)d_in[14];
    const float* g2 = (const float*)d_in[15];
    const float* b2 = (const float*)d_in[16];
    float* out = (float*)d_out;

    float *pX1, *pF, *pbqkv;
    __half *pAh, *pHh, *pBh;
    cudaGetSymbolAddress((void**)&pX1,  g_X1);
    cudaGetSymbolAddress((void**)&pF,   g_F);
    cudaGetSymbolAddress((void**)&pbqkv,g_bqkv);
    cudaGetSymbolAddress((void**)&pAh,  g_Ah);
    cudaGetSymbolAddress((void**)&pHh,  g_Hh);
    cudaGetSymbolAddress((void**)&pBh,  g_Bh);

    cudaFuncSetAttribute(attn_kernel, cudaFuncAttributeMaxDynamicSharedMemorySize, ATTN_SMEM);
    cudaFuncSetAttribute(gemm_tc_kernel, cudaFuncAttributeMaxDynamicSharedMemorySize, G_SMEM);

    dim3 blk(256);
    dim3 t32(32, 8);
    const int n4_1 = NTOK * HID / 4;
    dim3 gs1((n4_1 + 255) / 256);
    dim3 tg3(HID / 32, HID / 32, 3);
    dim3 tg11(HID / 32, HID / 32);
    dim3 tg14(4 * HID / 32, HID / 32);
    dim3 tg41(HID / 32, 4 * HID / 32);
    dim3 ggqkv(3 * HID / 128, NTOK / 128);
    dim3 gg1(HID / 128, NTOK / 128);
    dim3 gg4(4 * HID / 128, NTOK / 128);

    // ---- QKV: round x, batched W_{q,k,v}^T transpose, one N=3072 GEMM ----
    cvt_kernel<<<gs1, blk>>>(x, pAh, n4_1);
    tsplit3_kernel<<<tg3, t32>>>(Wq, Wk, Wv, pBh, HID, HID);
    cudaMemcpyAsync(pbqkv,        bq, HID * 4, cudaMemcpyDeviceToDevice, 0);
    cudaMemcpyAsync(pbqkv + 1024, bk, HID * 4, cudaMemcpyDeviceToDevice, 0);
    cudaMemcpyAsync(pbqkv + 2048, bv, HID * 4, cudaMemcpyDeviceToDevice, 0);
    gemm_tc_kernel<<<ggqkv, blk, G_SMEM>>>(pAh, pBh, pbqkv,
                                           nullptr, pHh,
                                           NTOK, 3 * HID, HID, 0);

    // ---- tensor-core attention; emits O fp16 ----
    attn_kernel<<<dim3(64, 4), 512, ATTN_SMEM>>>(pHh, pAh);

    // ---- output projection, residual + LN1 (emits X1 fp32 + fp16) ----
    tsplit_kernel<<<tg11, t32>>>(Wo, pBh, HID, HID);
    gemm_tc_kernel<<<gg1, blk, G_SMEM>>>(pAh, pBh, bo,
                                         pF, nullptr,
                                         NTOK, HID, HID, 0);
    ln_kernel<<<NTOK, blk>>>(pF, x, g1, b1, pX1, pAh);

    // ---- FFN ----
    tsplit_kernel<<<tg14, t32>>>(W1, pBh, HID, 4 * HID);
    gemm_tc_kernel<<<gg4, blk, G_SMEM>>>(pAh, pBh, c1,
                                         nullptr, pHh,
                                         NTOK, 4 * HID, HID, 1);
    tsplit_kernel<<<tg41, t32>>>(W2, pBh, 4 * HID, HID);
    gemm_tc_kernel<<<gg1, blk, G_SMEM>>>(pHh, pBh, c2,
                                         pF, nullptr,
                                         NTOK, HID, 4 * HID, 0);

    // ---- residual + LN2 -> output ----
    ln_kernel<<<NTOK, blk>>>(pF, pX1, g2, b2, out, nullptr);
}

// round 10
// speedup vs baseline: 3.2780x; 1.0354x over previous
#include <cuda_runtime.h>
#include <cuda_fp16.h>
#include <stdint.h>
#include <math.h>

// ---------------- scratch buffers (static device memory, no allocs) ----------
#define NTOK 4096              // 4 * 1024 rows
#define HID  1024
__device__ float g_X1 [NTOK * HID];
__device__ float g_F  [NTOK * HID];
__device__ float g_bqkv[3 * HID];
__device__ __half g_Ah[NTOK * HID];       // activations fp16 (x / O / X1)
__device__ __half g_Hh[NTOK * 4 * HID];   // QKV, later FF hidden
__device__ __half g_Bq[3 * HID * HID];    // W_{q,k,v}^T fp16
__device__ __half g_Bo[HID * HID];        // Wo^T
__device__ __half g_B1[4 * HID * HID];    // W1^T
__device__ __half g_B2[4 * HID * HID];    // W2^T

// ---------------- PTX helpers (arch-neutral only) -----------------------------
__device__ __forceinline__ uint32_t smem_u32(const void* p) {
    uint32_t a;
    asm("{ .reg .u64 t; cvta.to.shared.u64 t, %1; cvt.u32.u64 %0, t; }"
        : "=r"(a) : "l"(p));
    return a;
}
#define CP_ASYNC16(s, g) \
    asm volatile("cp.async.cg.shared.global [%0], [%1], 16;" :: "r"(s), "l"(g))
#define CP_COMMIT() asm volatile("cp.async.commit_group;" ::: "memory")
#define CP_WAIT(n)  asm volatile("cp.async.wait_group %0;" :: "n"(n) : "memory")
#define LDSM_X4(r, addr) \
    asm volatile("ldmatrix.sync.aligned.m8n8.x4.shared.b16 {%0,%1,%2,%3}, [%4];" \
        : "=r"((r)[0]), "=r"((r)[1]), "=r"((r)[2]), "=r"((r)[3]) : "r"(addr))
#define LDSM_X2(r, addr) \
    asm volatile("ldmatrix.sync.aligned.m8n8.x2.shared.b16 {%0,%1}, [%2];" \
        : "=r"((r)[0]), "=r"((r)[1]) : "r"(addr))
#define LDSM_X2T(r, addr) \
    asm volatile("ldmatrix.sync.aligned.m8n8.x2.trans.shared.b16 {%0,%1}, [%2];" \
        : "=r"((r)[0]), "=r"((r)[1]) : "r"(addr))
#define MMAF16(c, a, b0, b1) \
    asm volatile("mma.sync.aligned.m16n8k16.row.col.f32.f16.f16.f32 " \
        "{%0,%1,%2,%3}, {%4,%5,%6,%7}, {%8,%9}, {%0,%1,%2,%3};" \
        : "+f"((c)[0]), "+f"((c)[1]), "+f"((c)[2]), "+f"((c)[3]) \
        : "r"((a)[0]), "r"((a)[1]), "r"((a)[2]), "r"((a)[3]), "r"(b0), "r"(b1))

__device__ __forceinline__ uint32_t pack_h2f(float x, float y) {
    __half2 p = __halves2half2(__float2half_rn(x), __float2half_rn(y));
    return *reinterpret_cast<uint32_t*>(&p);
}

// ---------------- conversion kernels -----------------------------------------
// fp32 -> fp16
__global__ __launch_bounds__(256) void cvt_kernel(
    const float* __restrict__ A, __half* __restrict__ H, int n4)
{
    int i = blockIdx.x * 256 + threadIdx.x;
    if (i >= n4) return;
    float4 v = ((const float4*)A)[i];
    ((__half2*)H)[i * 2 + 0] = __halves2half2(__float2half_rn(v.x), __float2half_rn(v.y));
    ((__half2*)H)[i * 2 + 1] = __halves2half2(__float2half_rn(v.z), __float2half_rn(v.w));
}

// transpose+round one 32x32 tile of W [K x N] fp32 -> H [N x K] fp16
__device__ __forceinline__ void tsplit_tile(
    const float* __restrict__ W, __half* __restrict__ H,
    int K, int N, int bk, int bn, float (*t)[33])
{
    const int tx = threadIdx.x, ty = threadIdx.y;
    #pragma unroll
    for (int j = 0; j < 4; ++j)
        t[ty + j * 8][tx] = W[(size_t)(bk + ty + j * 8) * N + bn + tx];
    __syncthreads();
    #pragma unroll
    for (int j = 0; j < 4; ++j) {
        int r = ty + j * 8;
        H[(size_t)(bn + r) * K + bk + tx] = __float2half_rn(t[tx][r]);
    }
}

// batched QKV transpose: three [1024x1024] weights via blockIdx.z
__global__ __launch_bounds__(256) void tsplit3_kernel(
    const float* __restrict__ W0, const float* __restrict__ W1,
    const float* __restrict__ W2, __half* __restrict__ H)
{
    __shared__ float t[32][33];
    const float* W = (blockIdx.z == 0) ? W0 : (blockIdx.z == 1) ? W1 : W2;
    __half* Hd = H + (size_t)blockIdx.z * HID * HID;
    tsplit_tile(W, Hd, HID, HID, blockIdx.y * 32, blockIdx.x * 32, t);
}

// merged transpose of Wo [1024x1024], W1 [1024x4096], W2 [4096x1024]
__global__ __launch_bounds__(256) void tsplitAll_kernel(
    const float* __restrict__ Wo, const float* __restrict__ W1,
    const float* __restrict__ W2, __half* __restrict__ Ho,
    __half* __restrict__ H1, __half* __restrict__ H2)
{
    __shared__ float t[32][33];
    int id = blockIdx.x;
    if (id < 1024) {                       // Wo: K=1024, N=1024 (32x32 tiles)
        tsplit_tile(Wo, Ho, HID, HID, (id >> 5) * 32, (id & 31) * 32, t);
    } else if (id < 5120) {                // W1: K=1024, N=4096 (32 x 128)
        int i2 = id - 1024;
        tsplit_tile(W1, H1, HID, 4 * HID, (i2 >> 7) * 32, (i2 & 127) * 32, t);
    } else {                               // W2: K=4096, N=1024 (128 x 32)
        int i2 = id - 5120;
        tsplit_tile(W2, H2, 4 * HID, HID, (i2 >> 5) * 32, (i2 & 31) * 32, t);
    }
}

// ---------------- single-fp16 tensor-core GEMM (3-stage, 1 sync/k-tile) ------
// C = act(A @ B^T + bias); A [M,K] fp16, B [N,K] fp16, fp32 accum.
#define G_PART  8192
#define G_STAGE (2 * G_PART)     // 16 KB per stage
#define G_SMEM  (3 * G_STAGE)    // 48 KB ring

__global__ __launch_bounds__(256) void gemm_tc_kernel(
    const __half* __restrict__ Ah, const __half* __restrict__ Bh,
    const float* __restrict__ bias,
    float* __restrict__ Cf, __half* __restrict__ Ch,
    int M, int N, int K, int act)
{
    extern __shared__ char smem[];
    const uint32_t sb = smem_u32(smem);
    const int tid = threadIdx.x;
    const int wid = tid >> 5, lane = tid & 31;
    const int warp_m = wid >> 2, warp_n = wid & 3;
    const int bm = blockIdx.y * 128, bn = blockIdx.x * 128;

    float acc[4][4][4];
    #pragma unroll
    for (int i = 0; i < 4; ++i)
        #pragma unroll
        for (int j = 0; j < 4; ++j)
            #pragma unroll
            for (int r = 0; r < 4; ++r) acc[i][j][r] = 0.f;

    const int swz = (lane & 7) >> 1;
    const int rA = warp_m * 64 + ((lane >> 3) & 1) * 8 + (lane & 7);
    const int kA = lane >> 4;
    const int rB = warp_n * 32 + (lane >> 4) * 8 + (lane & 7);
    const int kB = (lane >> 3) & 1;

    const int nst = K >> 5;

    auto load_stage = [&](int j, int slot) {
        const uint32_t st = sb + (uint32_t)slot * G_STAGE;
        const int kc = j * 32;
        #pragma unroll
        for (int t = 0; t < 2; ++t) {
            int idx = tid + t * 256;
            int row = idx >> 2, ch = idx & 3;
            uint32_t so = (uint32_t)row * 64 + (uint32_t)((ch ^ ((row >> 1) & 3)) << 4);
            size_t ga = (size_t)(bm + row) * K + kc + ch * 8;
            size_t gb = (size_t)(bn + row) * K + kc + ch * 8;
            CP_ASYNC16(st + 0 * G_PART + so, Ah + ga);
            CP_ASYNC16(st + 1 * G_PART + so, Bh + gb);
        }
        CP_COMMIT();
    };

    load_stage(0, 0);
    load_stage(1, 1);

    int slot = 0, slot2 = 2;   // slot = j%3, slot2 = (j+2)%3
    for (int j = 0; j < nst; ++j) {
        if (j + 1 < nst) { CP_WAIT(1); }   // stage j complete
        else             { CP_WAIT(0); }
        __syncthreads();                    // everyone done with slot (j-1)%3 == slot2
        if (j + 2 < nst) load_stage(j + 2, slot2);

        const uint32_t st = sb + (uint32_t)slot * G_STAGE;
        #pragma unroll
        for (int ks = 0; ks < 2; ++ks) {
            uint32_t ah[4][4], bh[2][4];
            #pragma unroll
            for (int mt = 0; mt < 4; ++mt) {
                uint32_t ao = (uint32_t)(rA + mt * 16) * 64
                            + (uint32_t)(((ks * 2 + kA) ^ swz) << 4);
                LDSM_X4(ah[mt], st + 0 * G_PART + ao);
            }
            #pragma unroll
            for (int np = 0; np < 2; ++np) {
                uint32_t bo = (uint32_t)(rB + np * 16) * 64
                            + (uint32_t)(((ks * 2 + kB) ^ swz) << 4);
                LDSM_X4(bh[np], st + 1 * G_PART + bo);
            }
            #pragma unroll
            for (int mt = 0; mt < 4; ++mt)
                #pragma unroll
                for (int nt = 0; nt < 4; ++nt) {
                    const uint32_t* bhp = &bh[nt >> 1][(nt & 1) * 2];
                    MMAF16(acc[mt][nt], ah[mt], bhp[0], bhp[1]);
                }
        }
        slot  = (slot  == 2) ? 0 : slot  + 1;
        slot2 = (slot2 == 2) ? 0 : slot2 + 1;
    }

    // epilogue
    #pragma unroll
    for (int mt = 0; mt < 4; ++mt)
        #pragma unroll
        for (int nt = 0; nt < 4; ++nt) {
            int row0 = bm + warp_m * 64 + mt * 16 + (lane >> 2);
            int col  = bn + warp_n * 32 + nt * 8 + (lane & 3) * 2;
            float b0 = bias[col], b1 = bias[col + 1];
            float v[4];
            v[0] = acc[mt][nt][0] + b0;
            v[1] = acc[mt][nt][1] + b1;
            v[2] = acc[mt][nt][2] + b0;
            v[3] = acc[mt][nt][3] + b1;
            if (act) {
                #pragma unroll
                for (int r = 0; r < 4; ++r)
                    v[r] = 0.5f * v[r] * (1.f + erff(v[r] * 0.70710678118654752f));
            }
            if (Cf) {
                *(float2*)&Cf[(size_t)row0 * N + col]       = make_float2(v[0], v[1]);
                *(float2*)&Cf[(size_t)(row0 + 8) * N + col] = make_float2(v[2], v[3]);
            } else {
                uint32_t p0 = pack_h2f(v[0], v[1]);
                uint32_t p1 = pack_h2f(v[2], v[3]);
                *(uint32_t*)&Ch[(size_t)row0 * N + col]       = p0;
                *(uint32_t*)&Ch[(size_t)(row0 + 8) * N + col] = p1;
            }
        }
}

// ---------------- tensor-core attention (single fp16, head-axis softmax) ------
// QKV packed fp16 [4096][3072]. Per block (a, n): 16 warps, warp = head.
// 3 barriers per iteration; KV double-buffered, prefetch issued mid-iter.
#define SCW(hh, b, p) ((hh) * 290 + (b) * 18 + (p))
#define AT_STG 65536                 // K (32KB) + V (32KB) per stage
#define ATTN_SMEM (2 * AT_STG + 290 * 16 * 4)

__global__ __launch_bounds__(512, 1) void attn_kernel(
    const __half* __restrict__ Ph, __half* __restrict__ Oh)
{
    extern __shared__ char smem[];
    const uint32_t sb = smem_u32(smem);
    float* sc = (float*)(smem + 2 * AT_STG);

    const int tid = threadIdx.x, lane = tid & 31, h = tid >> 5;
    const int a = blockIdx.x, n = blockIdx.y;
    const int lr = lane >> 2, lc = lane & 3;

    // ---- stage Q into stage-0 area, extract fragments ----
    {
        #pragma unroll
        for (int t = 0; t < 4; ++t) {
            int f = tid + t * 512;
            int hh = f >> 7, bp = (f >> 3) & 15, c = f & 7;
            uint32_t dst = (uint32_t)hh * 2048 + bp * 128 + ((c ^ (bp & 7)) << 4);
            size_t src = (size_t)(n * 1024 + hh * 64 + a) * 3072 + bp * 64 + c * 8;
            CP_ASYNC16(sb + dst, Ph + src);
        }
        CP_COMMIT(); CP_WAIT(0); __syncthreads();
    }
    uint32_t qh[4][4];
    {
        int b = lane & 15, cs = lane >> 4;
        #pragma unroll
        for (int ks = 0; ks < 4; ++ks) {
            uint32_t ad = (uint32_t)h * 2048 + b * 128
                        + (((ks * 2 + cs) ^ (b & 7)) << 4);
            LDSM_X4(qh[ks], sb + ad);
        }
    }
    __syncthreads();   // everyone done reading Q before KV overwrites stage 0

    auto stageKV = [&](int ap, int s) {
        uint32_t base = sb + (uint32_t)s * AT_STG;
        #pragma unroll
        for (int t = 0; t < 4; ++t) {
            int f = tid + t * 512;
            int hh = f >> 7, bp = (f >> 3) & 15, c = f & 7;
            uint32_t dst = (uint32_t)hh * 2048 + bp * 128 + ((c ^ (bp & 7)) << 4);
            size_t row = (size_t)(n * 1024 + hh * 64 + ap) * 3072;
            CP_ASYNC16(base + dst,         Ph + row + 1024 + bp * 64 + c * 8);
            CP_ASYNC16(base + 32768 + dst, Ph + row + 2048 + bp * 64 + c * 8);
        }
        CP_COMMIT();
    };

    float o[8][4];
    #pragma unroll
    for (int nt = 0; nt < 8; ++nt)
        #pragma unroll
        for (int r = 0; r < 4; ++r) o[nt][r] = 0.f;

    stageKV(0, 0);
    for (int ap = 0; ap < 64; ++ap) {
        const int s = ap & 1;
        CP_WAIT(0);        // stage(ap) complete (only group in flight)
        __syncthreads();   // syncA: also fences AV(ap-1) reads of sc & slot s^1

        const uint32_t kb = sb + (uint32_t)s * AT_STG;
        const uint32_t vb = kb + 32768;

        // ---- scores: S = Q K^T ----
        float sv[2][4];
        #pragma unroll
        for (int nt = 0; nt < 2; ++nt)
            #pragma unroll
            for (int r = 0; r < 4; ++r) sv[nt][r] = 0.f;
        {
            int bpr = lane & 7, khalf = (lane >> 3) & 1;
            #pragma unroll
            for (int ks = 0; ks < 4; ++ks)
                #pragma unroll
                for (int nt = 0; nt < 2; ++nt) {
                    int row = nt * 8 + bpr;
                    uint32_t ad = (uint32_t)h * 2048 + row * 128
                                + (((ks * 2 + khalf) ^ (row & 7)) << 4);
                    uint32_t k2[2];
                    LDSM_X2(k2, kb + ad);
                    MMAF16(sv[nt], qh[ks], k2[0], k2[1]);
                }
        }
        #pragma unroll
        for (int nt = 0; nt < 2; ++nt) {
            int c0 = nt * 8 + 2 * lc;
            sc[SCW(h, lr,     c0)]     = sv[nt][0] * 0.03125f;
            sc[SCW(h, lr,     c0 + 1)] = sv[nt][1] * 0.03125f;
            sc[SCW(h, lr + 8, c0)]     = sv[nt][2] * 0.03125f;
            sc[SCW(h, lr + 8, c0 + 1)] = sv[nt][3] * 0.03125f;
        }
        __syncthreads();   // syncB: sc complete; slot s^1 drained (AV(ap-1) behind syncA)

        // prefetch next KV into slot s^1 (safe: last readers fenced above)
        if (ap + 1 < 64) stageKV(ap + 1, s ^ 1);

        // ---- head-softmax: thread p owns (b = p>>4, b' = p&15) ----
        if (tid < 256) {
            const int pb = tid >> 4, pbp = tid & 15;
            float m = -1e30f;
            #pragma unroll
            for (int hh = 0; hh < 16; ++hh) m = fmaxf(m, sc[SCW(hh, pb, pbp)]);
            float ssum = 0.f;
            #pragma unroll
            for (int hh = 0; hh < 16; ++hh) {
                float e = __expf(sc[SCW(hh, pb, pbp)] - m);
                ssum += e;
                sc[SCW(hh, pb, pbp)] = e;
            }
            float inv = 1.f / ssum;
            #pragma unroll
            for (int hh = 0; hh < 16; ++hh) sc[SCW(hh, pb, pbp)] *= inv;
        }
        __syncthreads();   // syncC: softmax done

        // ---- W fragments (fp16) from softmaxed scores ----
        uint32_t awh[4];
        awh[0] = pack_h2f(sc[SCW(h, lr,     2 * lc)],     sc[SCW(h, lr,     2 * lc + 1)]);
        awh[1] = pack_h2f(sc[SCW(h, lr + 8, 2 * lc)],     sc[SCW(h, lr + 8, 2 * lc + 1)]);
        awh[2] = pack_h2f(sc[SCW(h, lr,     2 * lc + 8)], sc[SCW(h, lr,     2 * lc + 9)]);
        awh[3] = pack_h2f(sc[SCW(h, lr + 8, 2 * lc + 8)], sc[SCW(h, lr + 8, 2 * lc + 9)]);

        // ---- AV: O += W V (V via ldmatrix.trans) ----
        {
            int bp = lane & 15;
            #pragma unroll
            for (int nt = 0; nt < 8; ++nt) {
                uint32_t ad = (uint32_t)h * 2048 + bp * 128
                            + ((nt ^ (bp & 7)) << 4);
                uint32_t v2[2];
                LDSM_X2T(v2, vb + ad);
                MMAF16(o[nt], awh, v2[0], v2[1]);
            }
        }
        // no end-of-loop barrier: next iter's syncA fences AV before overwrites
    }

    // ---- write O (one 1024-col row per head) as fp16 ----
    const size_t orow = (size_t)(n * 1024 + h * 64 + a) * 1024;
    #pragma unroll
    for (int nt = 0; nt < 8; ++nt) {
        int c0 = nt * 8 + 2 * lc;
        uint32_t p0 = pack_h2f(o[nt][0], o[nt][1]);
        uint32_t p1 = pack_h2f(o[nt][2], o[nt][3]);
        *(uint32_t*)(Oh + orow + lr * 64 + c0)       = p0;
        *(uint32_t*)(Oh + orow + (lr + 8) * 64 + c0) = p1;
    }
}

// ---------------- fused residual + LayerNorm (+ optional fp16 emit) ----------
__global__ __launch_bounds__(256) void ln_kernel(
    const float* __restrict__ A, const float* __restrict__ R,
    const float* __restrict__ g, const float* __restrict__ bta,
    float* __restrict__ out, __half* __restrict__ Xh)
{
    __shared__ float red[16];
    const int row = blockIdx.x;
    const int tid = threadIdx.x;

    float4 v = ((const float4*)(A + (size_t)row * 1024))[tid];
    float4 r = ((const float4*)(R + (size_t)row * 1024))[tid];
    v.x += r.x; v.y += r.y; v.z += r.z; v.w += r.w;

    float s  = v.x + v.y + v.z + v.w;
    float sq = v.x * v.x + v.y * v.y + v.z * v.z + v.w * v.w;
    #pragma unroll
    for (int o = 16; o > 0; o >>= 1) {
        s  += __shfl_xor_sync(0xffffffffu, s,  o);
        sq += __shfl_xor_sync(0xffffffffu, sq, o);
    }
    if ((tid & 31) == 0) { red[tid >> 5] = s; red[8 + (tid >> 5)] = sq; }
    __syncthreads();
    float S = 0.f, SQ = 0.f;
    #pragma unroll
    for (int w = 0; w < 8; ++w) { S += red[w]; SQ += red[8 + w]; }

    const float mean = S * (1.f / 1024.f);
    const float var  = SQ * (1.f / 1024.f) - mean * mean;
    const float rstd = rsqrtf(var + 1e-5f);

    float4 gv = ((const float4*)g)[tid];
    float4 bv = ((const float4*)bta)[tid];
    float4 o;
    o.x = (v.x - mean) * rstd * gv.x + bv.x;
    o.y = (v.y - mean) * rstd * gv.y + bv.y;
    o.z = (v.z - mean) * rstd * gv.z + bv.z;
    o.w = (v.w - mean) * rstd * gv.w + bv.w;
    ((float4*)(out + (size_t)row * 1024))[tid] = o;

    if (Xh) {
        size_t oo = (size_t)row * 1024 + tid * 4;
        *(__half2*)(Xh + oo)     = __halves2half2(__float2half_rn(o.x), __float2half_rn(o.y));
        *(__half2*)(Xh + oo + 2) = __halves2half2(__float2half_rn(o.z), __float2half_rn(o.w));
    }
}

// ---------------- launch ------------------------------------------------------
extern "C" void kernel_launch(void* const* d_in, const int* in_sizes, int n_in,
                              void* d_out, int out_size)
{
    const float* x  = (const float*)d_in[0];
    const float* Wq = (const float*)d_in[1];
    const float* bq = (const float*)d_in[2];
    const float* Wk = (const float*)d_in[3];
    const float* bk = (const float*)d_in[4];
    const float* Wv = (const float*)d_in[5];
    const float* bv = (const float*)d_in[6];
    const float* Wo = (const float*)d_in[7];
    const float* bo = (const float*)d_in[8];
    const float* g1 = (const float*)d_in[9];
    const float* b1 = (const float*)d_in[10];
    const float* W1 = (const float*)d_in[11];
    const float* c1 = (const float*)d_in[12];
    const float* W2 = (const float*)d_in[13];
    const float* c2 = (const float*)d_in[14];
    const float* g2 = (const float*)d_in[15];
    const float* b2 = (const float*)d_in[16];
    float* out = (float*)d_out;

    float *pX1, *pF, *pbqkv;
    __half *pAh, *pHh, *pBq, *pBo, *pB1, *pB2;
    cudaGetSymbolAddress((void**)&pX1,  g_X1);
    cudaGetSymbolAddress((void**)&pF,   g_F);
    cudaGetSymbolAddress((void**)&pbqkv,g_bqkv);
    cudaGetSymbolAddress((void**)&pAh,  g_Ah);
    cudaGetSymbolAddress((void**)&pHh,  g_Hh);
    cudaGetSymbolAddress((void**)&pBq,  g_Bq);
    cudaGetSymbolAddress((void**)&pBo,  g_Bo);
    cudaGetSymbolAddress((void**)&pB1,  g_B1);
    cudaGetSymbolAddress((void**)&pB2,  g_B2);

    cudaFuncSetAttribute(attn_kernel, cudaFuncAttributeMaxDynamicSharedMemorySize, ATTN_SMEM);
    cudaFuncSetAttribute(gemm_tc_kernel, cudaFuncAttributeMaxDynamicSharedMemorySize, G_SMEM);

    dim3 blk(256);
    dim3 t32(32, 8);
    const int n4_1 = NTOK * HID / 4;
    dim3 gs1((n4_1 + 255) / 256);
    dim3 tg3(HID / 32, HID / 32, 3);
    dim3 ggqkv(3 * HID / 128, NTOK / 128);
    dim3 gg1(HID / 128, NTOK / 128);
    dim3 gg4(4 * HID / 128, NTOK / 128);

    // ---- conversions: x, W_{q,k,v}^T, and all remaining weights up front ----
    cvt_kernel<<<gs1, blk>>>(x, pAh, n4_1);
    tsplit3_kernel<<<tg3, t32>>>(Wq, Wk, Wv, pBq);
    tsplitAll_kernel<<<9216, t32>>>(Wo, W1, W2, pBo, pB1, pB2);
    cudaMemcpyAsync(pbqkv,        bq, HID * 4, cudaMemcpyDeviceToDevice, 0);
    cudaMemcpyAsync(pbqkv + 1024, bk, HID * 4, cudaMemcpyDeviceToDevice, 0);
    cudaMemcpyAsync(pbqkv + 2048, bv, HID * 4, cudaMemcpyDeviceToDevice, 0);

    // ---- QKV GEMM (N=3072) -> fp16 ----
    gemm_tc_kernel<<<ggqkv, blk, G_SMEM>>>(pAh, pBq, pbqkv,
                                           nullptr, pHh,
                                           NTOK, 3 * HID, HID, 0);

    // ---- tensor-core attention; emits O fp16 ----
    attn_kernel<<<dim3(64, 4), 512, ATTN_SMEM>>>(pHh, pAh);

    // ---- output projection, residual + LN1 (emits X1 fp32 + fp16) ----
    gemm_tc_kernel<<<gg1, blk, G_SMEM>>>(pAh, pBo, bo,
                                         pF, nullptr,
                                         NTOK, HID, HID, 0);
    ln_kernel<<<NTOK, blk>>>(pF, x, g1, b1, pX1, pAh);

    // ---- FFN ----
    gemm_tc_kernel<<<gg4, blk, G_SMEM>>>(pAh, pB1, c1,
                                         nullptr, pHh,
                                         NTOK, 4 * HID, HID, 1);
    gemm_tc_kernel<<<gg1, blk, G_SMEM>>>(pHh, pB2, c2,
                                         pF, nullptr,
                                         NTOK, HID, 4 * HID, 0);

    // ---- residual + LN2 -> output ----
    ln_kernel<<<NTOK, blk>>>(pF, pX1, g2, b2, out, nullptr);
}